// round 12
// baseline (speedup 1.0000x reference)
#include <cuda_runtime.h>
#include <cuda_bf16.h>
#include <cstdint>

#define B_  8
#define S1_ 2048
#define S2_ 2048
#define D_  512
#define F_  256
#define NQKV (B_ * S1_ * F_)
#define NFEAT (B_ * S1_ * D_)
#define NP   (B_ * S1_ * S2_)

__device__ __align__(16) __nv_bfloat16 g_f1h[NFEAT];
__device__ __align__(16) __nv_bfloat16 g_f1l[NFEAT];
__device__ __align__(16) __nv_bfloat16 g_f2h[NFEAT];
__device__ __align__(16) __nv_bfloat16 g_f2l[NFEAT];
__device__ __align__(16) __nv_bfloat16 g_wq[2][D_ * F_];
__device__ __align__(16) __nv_bfloat16 g_wk[2][D_ * F_];
__device__ __align__(16) __nv_bfloat16 g_w2[2][D_ * F_];   // (Wv@Wfc)^T split
__device__ __align__(16) float         g_c2[F_];           // bv@Wfc + bfc
__device__ __align__(16) float         g_zero[F_];         // zero-initialized
__device__ __align__(16) __nv_bfloat16 g_Qh [NQKV];
__device__ __align__(16) __nv_bfloat16 g_Ql [NQKV];
__device__ __align__(16) __nv_bfloat16 g_Kh [NQKV];
__device__ __align__(16) __nv_bfloat16 g_Kl [NQKV];
__device__ __align__(16) __nv_bfloat16 g_VTh[NQKV];        // [b, f, t] of feat2@W2
__device__ __align__(16) __nv_bfloat16 g_VTl[NQKV];
__device__ __align__(16) __nv_bfloat16 g_Ph [NP];
__device__ __align__(16) __nv_bfloat16 g_Pl [NP];
__device__ __align__(16) float         g_lp [B_ * S1_ * 16];
__device__ __align__(16) float         g_l  [B_ * S1_];

__device__ __forceinline__ uint32_t smem_to_u32(const void* p) {
    uint32_t a;
    asm("{ .reg .u64 t; cvta.to.shared.u64 t, %1; cvt.u32.u64 %0, t; }" : "=r"(a) : "l"(p));
    return a;
}
__device__ __forceinline__ void ldsm4(uint32_t* r, uint32_t a) {
    asm volatile("ldmatrix.sync.aligned.m8n8.x4.shared.b16 {%0,%1,%2,%3}, [%4];"
        : "=r"(r[0]), "=r"(r[1]), "=r"(r[2]), "=r"(r[3]) : "r"(a));
}
__device__ __forceinline__ void mma_bf16(float (&d)[4], const uint32_t* a, uint32_t b0, uint32_t b1) {
    asm volatile("mma.sync.aligned.m16n8k16.row.col.f32.bf16.bf16.f32 "
        "{%0,%1,%2,%3}, {%4,%5,%6,%7}, {%8,%9}, {%0,%1,%2,%3};"
        : "+f"(d[0]), "+f"(d[1]), "+f"(d[2]), "+f"(d[3])
        : "r"(a[0]), "r"(a[1]), "r"(a[2]), "r"(a[3]), "r"(b0), "r"(b1));
}
__device__ __forceinline__ void split_bf16(float x, __nv_bfloat16& h, __nv_bfloat16& l) {
    h = __float2bfloat16(x);
    l = __float2bfloat16(x - __bfloat162float(h));
}
__device__ __forceinline__ uint32_t pack2(__nv_bfloat16 a, __nv_bfloat16 b) {
    return (uint32_t)__bfloat16_as_ushort(a) | ((uint32_t)__bfloat16_as_ushort(b) << 16);
}
#define CP_ASYNC16(dst, src) asm volatile("cp.async.cg.shared.global [%0], [%1], 16;" :: "r"(dst), "l"(src))
#define CP_COMMIT() asm volatile("cp.async.commit_group;" ::: "memory")
#define CP_WAIT0()  asm volatile("cp.async.wait_group 0;" ::: "memory")
#define CP_WAIT1()  asm volatile("cp.async.wait_group 1;" ::: "memory")

__global__ void __launch_bounds__(256) split_f32_kernel(
    const float* __restrict__ in, __nv_bfloat16* __restrict__ h,
    __nv_bfloat16* __restrict__ l, int n4)
{
    int i = blockIdx.x * 256 + threadIdx.x;
    if (i >= n4) return;
    float4 v = ((const float4*)in)[i];
    __nv_bfloat16 h0,l0,h1,l1,h2,l2,h3,l3;
    split_bf16(v.x,h0,l0); split_bf16(v.y,h1,l1);
    split_bf16(v.z,h2,l2); split_bf16(v.w,h3,l3);
    ((uint2*)h)[i] = make_uint2(pack2(h0,h1), pack2(h2,h3));
    ((uint2*)l)[i] = make_uint2(pack2(l0,l1), pack2(l2,l3));
}

// Wq, Wk: split + transpose.
__global__ void __launch_bounds__(256) split_weights_kernel(
    const float* __restrict__ Wq, const float* __restrict__ Wk,
    __nv_bfloat16* __restrict__ wq0, __nv_bfloat16* __restrict__ wq1,
    __nv_bfloat16* __restrict__ wk0, __nv_bfloat16* __restrict__ wk1)
{
    int i = blockIdx.x * 256 + threadIdx.x;
    const int NW = D_ * F_;
    if (i >= 2 * NW) return;
    int which = i / NW, j = i - which * NW;
    int n = j / D_, k = j - n * D_;
    const float* W = which == 0 ? Wq : Wk;
    __nv_bfloat16 h, l;
    split_bf16(W[(size_t)k * F_ + n], h, l);
    (which == 0 ? wq0 : wk0)[j] = h;
    (which == 0 ? wq1 : wk1)[j] = l;
}

// W2 = Wv @ Wfc (fp32, then split+transpose); c2 = bv@Wfc + bfc.
// grid 65 blocks x 256 thr. Blocks 0..63: 8 k-rows each. Block 64: c2.
__global__ void __launch_bounds__(256) w2c2_kernel(
    const float* __restrict__ Wv, const float* __restrict__ Wfc,
    const float* __restrict__ bv, const float* __restrict__ bfc,
    __nv_bfloat16* __restrict__ w2h, __nv_bfloat16* __restrict__ w2l,
    float* __restrict__ c2)
{
    const int n = threadIdx.x;
    const int kb = blockIdx.x;
    if (kb == 64) {
        float s = bfc[n];
        for (int j = 0; j < F_; j++) s += bv[j] * Wfc[(size_t)j * F_ + n];
        c2[n] = s;
        return;
    }
    __shared__ float wv[8][F_];
    #pragma unroll
    for (int r = 0; r < 8; r++) wv[r][n] = Wv[(size_t)(kb * 8 + r) * F_ + n];
    __syncthreads();
    float s[8] = {0,0,0,0,0,0,0,0};
    for (int j = 0; j < F_; j++) {
        float wf = Wfc[(size_t)j * F_ + n];
        #pragma unroll
        for (int r = 0; r < 8; r++) s[r] += wv[r][j] * wf;
    }
    #pragma unroll
    for (int r = 0; r < 8; r++) {
        __nv_bfloat16 h, l;
        split_bf16(s[r], h, l);
        size_t idx = (size_t)n * D_ + kb * 8 + r;   // transposed [n][k]
        w2h[idx] = h; w2l[idx] = l;
    }
}

// ---------------------------------------------------------------------------
// Shared HMMA GEMM body: CTA 128x128, 8 warps (2m x 4n), warp 64x32,
// k-block 32, 3-stage cp.async (96KB smem), packed hi|lo 128B rows.
// ---------------------------------------------------------------------------
#define GEMM_SMEM 98304

#define GEMM_PROLOG \
    extern __shared__ char sm[]; \
    const uint32_t smb = smem_to_u32(sm); \
    const int tid = threadIdx.x, lane = tid & 31, wid = tid >> 5; \
    const int wm = wid & 1, wn = wid >> 1; \
    const int arow = wm * 64 + (lane & 15); \
    const int as = arow & 7, ah = lane >> 4; \
    const int brow = wn * 32 + ((lane >> 4) << 3) + (lane & 7); \
    const int bs = lane & 7, bh2 = (lane >> 3) & 1; \
    const int lq = lane & 3;

#define GISSUE(buf, k0, KDV) do { \
    uint32_t gb = smb + (buf) * 32768; \
    _Pragma("unroll") \
    for (int p = 0; p < 4; p++) { \
        int id = p * 256 + tid; int r = id >> 3, c = id & 7; \
        uint32_t d = r * 128 + (((uint32_t)(c ^ (r & 7))) << 4); \
        const __nv_bfloat16* sa = (c < 4) ? Ah + (size_t)(ma + r) * (KDV) + (k0) + c * 8 \
                                          : Al + (size_t)(ma + r) * (KDV) + (k0) + (c - 4) * 8; \
        CP_ASYNC16(gb + d, sa); \
        const __nv_bfloat16* sb = (c < 4) ? Bh + (size_t)(nb + r) * (KDV) + (k0) + c * 8 \
                                          : Bl + (size_t)(nb + r) * (KDV) + (k0) + (c - 4) * 8; \
        CP_ASYNC16(gb + 16384 + d, sb); \
    } } while (0)

#define GEMM_MAIN(KDV) \
    float acc[4][4][4]; \
    _Pragma("unroll") \
    for (int i = 0; i < 4; i++) \
        _Pragma("unroll") \
        for (int j = 0; j < 4; j++) \
            _Pragma("unroll") \
            for (int k = 0; k < 4; k++) acc[i][j][k] = 0.f; \
    { \
        const int T = (KDV) / 32; \
        GISSUE(0, 0, KDV); CP_COMMIT(); \
        if (T > 1) { GISSUE(1, 32, KDV); CP_COMMIT(); } \
        for (int t = 0; t < T; t++) { \
            if (t + 1 < T) { CP_WAIT1(); } else { CP_WAIT0(); } \
            __syncthreads(); \
            if (t + 2 < T) { GISSUE((t + 2) % 3, (t + 2) * 32, KDV); CP_COMMIT(); } \
            const int cur = t % 3; \
            uint32_t aP = smb + cur * 32768 + arow * 128; \
            uint32_t bP = smb + cur * 32768 + 16384 + brow * 128; \
            _Pragma("unroll") \
            for (int ks = 0; ks < 2; ks++) { \
                uint32_t hcA = (uint32_t)(2 * ks + ah); \
                uint32_t aq[4][4], alr[4][4]; \
                _Pragma("unroll") \
                for (int mi = 0; mi < 4; mi++) { \
                    ldsm4(aq[mi],  aP + mi * 2048 + ((hcA ^ (uint32_t)as) << 4)); \
                    ldsm4(alr[mi], aP + mi * 2048 + (((hcA + 4) ^ (uint32_t)as) << 4)); \
                } \
                uint32_t hcB = (uint32_t)(2 * ks + bh2); \
                _Pragma("unroll") \
                for (int ni = 0; ni < 2; ni++) { \
                    uint32_t bhh[4], bll[4]; \
                    ldsm4(bhh, bP + ni * 2048 + ((hcB ^ (uint32_t)bs) << 4)); \
                    ldsm4(bll, bP + ni * 2048 + (((hcB + 4) ^ (uint32_t)bs) << 4)); \
                    _Pragma("unroll") \
                    for (int mi = 0; mi < 4; mi++) { \
                        mma_bf16(acc[mi][2*ni],   aq[mi],  bhh[0], bhh[1]); \
                        mma_bf16(acc[mi][2*ni],   aq[mi],  bll[0], bll[1]); \
                        mma_bf16(acc[mi][2*ni],   alr[mi], bhh[0], bhh[1]); \
                        mma_bf16(acc[mi][2*ni+1], aq[mi],  bhh[2], bhh[3]); \
                        mma_bf16(acc[mi][2*ni+1], aq[mi],  bll[2], bll[3]); \
                        mma_bf16(acc[mi][2*ni+1], alr[mi], bhh[2], bhh[3]); \
                    } \
                } \
            } \
        } \
        __syncthreads(); \
    }

// ---------------------------------------------------------------------------
// Fused Q/K/V' projection GEMM: z selects product (V' = feat2 @ Wv@Wfc).
// ---------------------------------------------------------------------------
__global__ void __launch_bounds__(256, 2) gemm_qkv(
    const __nv_bfloat16* __restrict__ f1h, const __nv_bfloat16* __restrict__ f1l,
    const __nv_bfloat16* __restrict__ f2h, const __nv_bfloat16* __restrict__ f2l,
    const __nv_bfloat16* __restrict__ wqh, const __nv_bfloat16* __restrict__ wql,
    const __nv_bfloat16* __restrict__ wkh, const __nv_bfloat16* __restrict__ wkl,
    const __nv_bfloat16* __restrict__ w2h, const __nv_bfloat16* __restrict__ w2l,
    const float* __restrict__ bq, const float* __restrict__ bk, const float* __restrict__ bz,
    __nv_bfloat16* __restrict__ Qh, __nv_bfloat16* __restrict__ Ql,
    __nv_bfloat16* __restrict__ Kh, __nv_bfloat16* __restrict__ Kl,
    __nv_bfloat16* __restrict__ VTh, __nv_bfloat16* __restrict__ VTl)
{
    GEMM_PROLOG
    const int n0 = blockIdx.x * 128, m0 = blockIdx.y * 128;
    const int z = blockIdx.z;
    const int ma = m0, nb = n0;
    const __nv_bfloat16* Ah = z == 0 ? f1h : f2h;
    const __nv_bfloat16* Al = z == 0 ? f1l : f2l;
    const __nv_bfloat16* Bh = z == 0 ? wqh : (z == 1 ? wkh : w2h);
    const __nv_bfloat16* Bl = z == 0 ? wql : (z == 1 ? wkl : w2l);
    const float* bias = z == 0 ? bq : (z == 1 ? bk : bz);
    __nv_bfloat16* Oh = z == 0 ? Qh : (z == 1 ? Kh : VTh);
    __nv_bfloat16* Ol = z == 0 ? Ql : (z == 1 ? Kl : VTl);

    GEMM_MAIN(D_)

    #pragma unroll
    for (int mi = 0; mi < 4; mi++) {
        int r0 = m0 + wm * 64 + mi * 16 + (lane >> 2);
        int r1 = r0 + 8;
        #pragma unroll
        for (int nt = 0; nt < 4; nt++) {
            int col = n0 + wn * 32 + nt * 8 + 2 * lq;
            float b0 = bias[col], b1 = bias[col + 1];
            float v0 = acc[mi][nt][0] + b0, v1 = acc[mi][nt][1] + b1;
            float v2 = acc[mi][nt][2] + b0, v3 = acc[mi][nt][3] + b1;
            __nv_bfloat16 h0,l0,h1,l1,h2,l2,h3,l3;
            split_bf16(v0,h0,l0); split_bf16(v1,h1,l1);
            split_bf16(v2,h2,l2); split_bf16(v3,h3,l3);
            if (z < 2) {
                size_t o0 = (size_t)r0 * 256 + col, o1 = (size_t)r1 * 256 + col;
                *(uint32_t*)(Oh + o0) = pack2(h0, h1);
                *(uint32_t*)(Ol + o0) = pack2(l0, l1);
                *(uint32_t*)(Oh + o1) = pack2(h2, h3);
                *(uint32_t*)(Ol + o1) = pack2(l2, l3);
            } else {
                size_t o0 = (size_t)(r0 >> 11) * (F_ * S2_) + (size_t)col * S2_ + (r0 & 2047);
                size_t o1 = (size_t)(r1 >> 11) * (F_ * S2_) + (size_t)col * S2_ + (r1 & 2047);
                Oh[o0] = h0; Oh[o0 + S2_] = h1; Ol[o0] = l0; Ol[o0 + S2_] = l1;
                Oh[o1] = h2; Oh[o1 + S2_] = h3; Ol[o1] = l2; Ol[o1 + S2_] = l3;
            }
        }
    }
}

// ---------------------------------------------------------------------------
// S-kernel: P = exp(scale * Q@K^T) split-bf16 + per-128-block row sums.
// ---------------------------------------------------------------------------
__global__ void __launch_bounds__(256, 2) gemm_S(
    const __nv_bfloat16* __restrict__ Qh, const __nv_bfloat16* __restrict__ Ql,
    const __nv_bfloat16* __restrict__ Kh, const __nv_bfloat16* __restrict__ Kl,
    __nv_bfloat16* __restrict__ Ph, __nv_bfloat16* __restrict__ Pl,
    float* __restrict__ lp)
{
    GEMM_PROLOG
    const int kblk = blockIdx.x, qblk = blockIdx.y, b = blockIdx.z;
    const int ma = qblk * 128, nb = kblk * 128;
    const __nv_bfloat16* Ah = Qh + (size_t)b * S1_ * F_;
    const __nv_bfloat16* Al = Ql + (size_t)b * S1_ * F_;
    const __nv_bfloat16* Bh = Kh + (size_t)b * S2_ * F_;
    const __nv_bfloat16* Bl = Kl + (size_t)b * S2_ * F_;

    GEMM_MAIN(F_)

    const float scale = 0.0625f;
    const int bq0 = b * S1_ + qblk * 128;
    const int kb0 = kblk * 128;
    float rsum[4][2];
    #pragma unroll
    for (int mi = 0; mi < 4; mi++) { rsum[mi][0] = 0.f; rsum[mi][1] = 0.f; }

    #pragma unroll
    for (int mi = 0; mi < 4; mi++) {
        int rl0 = wm * 64 + mi * 16 + (lane >> 2);
        size_t pb0 = (size_t)(bq0 + rl0) * S2_ + kb0;
        size_t pb1 = (size_t)(bq0 + rl0 + 8) * S2_ + kb0;
        #pragma unroll
        for (int nt = 0; nt < 4; nt++) {
            int col = wn * 32 + nt * 8 + 2 * lq;
            float p0 = __expf(acc[mi][nt][0] * scale);
            float p1 = __expf(acc[mi][nt][1] * scale);
            float p2 = __expf(acc[mi][nt][2] * scale);
            float p3 = __expf(acc[mi][nt][3] * scale);
            rsum[mi][0] += p0 + p1;
            rsum[mi][1] += p2 + p3;
            __nv_bfloat16 h0,l0,h1,l1,h2,l2,h3,l3;
            split_bf16(p0,h0,l0); split_bf16(p1,h1,l1);
            split_bf16(p2,h2,l2); split_bf16(p3,h3,l3);
            *(uint32_t*)(Ph + pb0 + col) = pack2(h0, h1);
            *(uint32_t*)(Pl + pb0 + col) = pack2(l0, l1);
            *(uint32_t*)(Ph + pb1 + col) = pack2(h2, h3);
            *(uint32_t*)(Pl + pb1 + col) = pack2(l2, l3);
        }
    }
    #pragma unroll
    for (int mi = 0; mi < 4; mi++) {
        #pragma unroll
        for (int u = 0; u < 2; u++) {
            rsum[mi][u] += __shfl_xor_sync(0xffffffffu, rsum[mi][u], 1);
            rsum[mi][u] += __shfl_xor_sync(0xffffffffu, rsum[mi][u], 2);
        }
    }
    float* red = (float*)sm;
    __syncthreads();
    if (lq == 0) {
        #pragma unroll
        for (int mi = 0; mi < 4; mi++) {
            int rl = wm * 64 + mi * 16 + (lane >> 2);
            red[wn * 128 + rl]     = rsum[mi][0];
            red[wn * 128 + rl + 8] = rsum[mi][1];
        }
    }
    __syncthreads();
    if (tid < 128)
        lp[(size_t)(bq0 + tid) * 16 + kblk] =
            (red[tid] + red[128 + tid]) + (red[256 + tid] + red[384 + tid]);
}

__global__ void __launch_bounds__(256) lreduce_kernel(const float* __restrict__ lp,
                                                      float* __restrict__ l)
{
    int i = blockIdx.x * 256 + threadIdx.x;
    if (i >= B_ * S1_) return;
    float s = 0.f;
    #pragma unroll
    for (int j = 0; j < 16; j++) s += lp[(size_t)i * 16 + j];
    l[i] = s;
}

// ---------------------------------------------------------------------------
// PV-kernel: out = (P@VT'^T)/l + c2  (final fp32 output, FC folded in)
// ---------------------------------------------------------------------------
__global__ void __launch_bounds__(256, 2) gemm_pv(
    const __nv_bfloat16* __restrict__ Ph, const __nv_bfloat16* __restrict__ Pl,
    const __nv_bfloat16* __restrict__ VTh, const __nv_bfloat16* __restrict__ VTl,
    const float* __restrict__ l, const float* __restrict__ c2,
    float* __restrict__ out)
{
    GEMM_PROLOG
    const int fblk = blockIdx.x, qblk = blockIdx.y, b = blockIdx.z;
    const int ma = qblk * 128, nb = fblk * 128;
    const __nv_bfloat16* Ah = Ph + (size_t)b * S1_ * S2_;
    const __nv_bfloat16* Al = Pl + (size_t)b * S1_ * S2_;
    const __nv_bfloat16* Bh = VTh + (size_t)b * F_ * S2_;
    const __nv_bfloat16* Bl = VTl + (size_t)b * F_ * S2_;

    GEMM_MAIN(S2_)

    const int bq0 = b * S1_ + qblk * 128;
    #pragma unroll
    for (int mi = 0; mi < 4; mi++) {
        int rl0 = wm * 64 + mi * 16 + (lane >> 2);
        float inv0 = 1.f / l[bq0 + rl0];
        float inv1 = 1.f / l[bq0 + rl0 + 8];
        size_t o0 = (size_t)(bq0 + rl0) * 256;
        size_t o1 = (size_t)(bq0 + rl0 + 8) * 256;
        #pragma unroll
        for (int nt = 0; nt < 4; nt++) {
            int col = fblk * 128 + wn * 32 + nt * 8 + 2 * lq;
            float c0 = c2[col], c1 = c2[col + 1];
            *(float2*)(out + o0 + col) =
                make_float2(acc[mi][nt][0] * inv0 + c0, acc[mi][nt][1] * inv0 + c1);
            *(float2*)(out + o1 + col) =
                make_float2(acc[mi][nt][2] * inv1 + c0, acc[mi][nt][3] * inv1 + c1);
        }
    }
}

// ---------------------------------------------------------------------------
extern "C" void kernel_launch(void* const* d_in, const int* in_sizes, int n_in,
                              void* d_out, int out_size)
{
    const float* feat1 = (const float*)d_in[0];
    const float* feat2 = (const float*)d_in[1];
    const float* Wq    = (const float*)d_in[2];
    const float* bq    = (const float*)d_in[3];
    const float* Wk    = (const float*)d_in[4];
    const float* bk    = (const float*)d_in[5];
    const float* Wv    = (const float*)d_in[6];
    const float* bv    = (const float*)d_in[7];
    const float* Wfc   = (const float*)d_in[8];
    const float* bfc   = (const float*)d_in[9];
    float* out = (float*)d_out;

    __nv_bfloat16 *f1h, *f1l, *f2h, *f2l, *Qh, *Ql, *Kh, *Kl, *VTh, *VTl, *Ph, *Pl;
    float *lp, *lv, *c2, *zv;
    __nv_bfloat16 (*wq)[D_ * F_]; __nv_bfloat16 (*wk)[D_ * F_]; __nv_bfloat16 (*w2)[D_ * F_];
    cudaGetSymbolAddress((void**)&f1h, g_f1h);
    cudaGetSymbolAddress((void**)&f1l, g_f1l);
    cudaGetSymbolAddress((void**)&f2h, g_f2h);
    cudaGetSymbolAddress((void**)&f2l, g_f2l);
    cudaGetSymbolAddress((void**)&wq,  g_wq);
    cudaGetSymbolAddress((void**)&wk,  g_wk);
    cudaGetSymbolAddress((void**)&w2,  g_w2);
    cudaGetSymbolAddress((void**)&c2,  g_c2);
    cudaGetSymbolAddress((void**)&zv,  g_zero);
    cudaGetSymbolAddress((void**)&Qh,  g_Qh);
    cudaGetSymbolAddress((void**)&Ql,  g_Ql);
    cudaGetSymbolAddress((void**)&Kh,  g_Kh);
    cudaGetSymbolAddress((void**)&Kl,  g_Kl);
    cudaGetSymbolAddress((void**)&VTh, g_VTh);
    cudaGetSymbolAddress((void**)&VTl, g_VTl);
    cudaGetSymbolAddress((void**)&Ph,  g_Ph);
    cudaGetSymbolAddress((void**)&Pl,  g_Pl);
    cudaGetSymbolAddress((void**)&lp,  g_lp);
    cudaGetSymbolAddress((void**)&lv,  g_l);

    split_f32_kernel<<<NFEAT / 4 / 256, 256>>>(feat1, f1h, f1l, NFEAT / 4);
    split_f32_kernel<<<NFEAT / 4 / 256, 256>>>(feat2, f2h, f2l, NFEAT / 4);
    split_weights_kernel<<<(2 * D_ * F_ + 255) / 256, 256>>>(Wq, Wk, wq[0], wq[1], wk[0], wk[1]);
    w2c2_kernel<<<65, 256>>>(Wv, Wfc, bv, bfc, w2[0], w2[1], c2);

    cudaFuncSetAttribute(gemm_qkv, cudaFuncAttributeMaxDynamicSharedMemorySize, GEMM_SMEM);
    cudaFuncSetAttribute(gemm_S,   cudaFuncAttributeMaxDynamicSharedMemorySize, GEMM_SMEM);
    cudaFuncSetAttribute(gemm_pv,  cudaFuncAttributeMaxDynamicSharedMemorySize, GEMM_SMEM);

    dim3 gq(2, B_ * S1_ / 128, 3);
    gemm_qkv<<<gq, 256, GEMM_SMEM>>>(f1h, f1l, f2h, f2l,
                                     wq[0], wq[1], wk[0], wk[1], w2[0], w2[1],
                                     bq, bk, zv, Qh, Ql, Kh, Kl, VTh, VTl);

    dim3 gs(S2_ / 128, S1_ / 128, B_);
    gemm_S<<<gs, 256, GEMM_SMEM>>>(Qh, Ql, Kh, Kl, Ph, Pl, lp);

    lreduce_kernel<<<(B_ * S1_ + 255) / 256, 256>>>(lp, lv);

    dim3 gp(F_ / 128, S1_ / 128, B_);
    gemm_pv<<<gp, 256, GEMM_SMEM>>>(Ph, Pl, VTh, VTl, lv, c2, out);
}

// round 13
// speedup vs baseline: 1.3423x; 1.3423x over previous
#include <cuda_runtime.h>
#include <cuda_fp16.h>
#include <cstdint>

#define B_  8
#define S1_ 2048
#define S2_ 2048
#define D_  512
#define F_  256
#define NQKV (B_ * S1_ * F_)
#define NFEAT (B_ * S1_ * D_)
#define NP   (B_ * S1_ * S2_)

__device__ __align__(16) __half g_f1h[NFEAT];
__device__ __align__(16) __half g_f1l[NFEAT];
__device__ __align__(16) __half g_f2h[NFEAT];
__device__ __align__(16) __half g_f2l[NFEAT];
__device__ __align__(16) __half g_wq[2][D_ * F_];
__device__ __align__(16) __half g_wk[2][D_ * F_];
__device__ __align__(16) __half g_w2[2][D_ * F_];   // (Wv@Wfc)^T split
__device__ __align__(16) float  g_c2[F_];           // bv@Wfc + bfc
__device__ __align__(16) float  g_zero[F_];
__device__ __align__(16) __half g_Q  [NQKV];        // plain fp16
__device__ __align__(16) __half g_Kh [NQKV];
__device__ __align__(16) __half g_Kl [NQKV];
__device__ __align__(16) __half g_VTh[NQKV];        // [b, f, t] of feat2@W2
__device__ __align__(16) __half g_VTl[NQKV];
__device__ __align__(16) __half g_P  [NP];          // plain fp16
__device__ __align__(16) float  g_lp [B_ * S1_ * 16];
__device__ __align__(16) float  g_l  [B_ * S1_];

__device__ __forceinline__ uint32_t smem_to_u32(const void* p) {
    uint32_t a;
    asm("{ .reg .u64 t; cvta.to.shared.u64 t, %1; cvt.u32.u64 %0, t; }" : "=r"(a) : "l"(p));
    return a;
}
__device__ __forceinline__ void ldsm4(uint32_t* r, uint32_t a) {
    asm volatile("ldmatrix.sync.aligned.m8n8.x4.shared.b16 {%0,%1,%2,%3}, [%4];"
        : "=r"(r[0]), "=r"(r[1]), "=r"(r[2]), "=r"(r[3]) : "r"(a));
}
__device__ __forceinline__ void mma_f16(float (&d)[4], const uint32_t* a, uint32_t b0, uint32_t b1) {
    asm volatile("mma.sync.aligned.m16n8k16.row.col.f32.f16.f16.f32 "
        "{%0,%1,%2,%3}, {%4,%5,%6,%7}, {%8,%9}, {%0,%1,%2,%3};"
        : "+f"(d[0]), "+f"(d[1]), "+f"(d[2]), "+f"(d[3])
        : "r"(a[0]), "r"(a[1]), "r"(a[2]), "r"(a[3]), "r"(b0), "r"(b1));
}
__device__ __forceinline__ void split_h(float x, __half& h, __half& l) {
    h = __float2half_rn(x);
    l = __float2half_rn(x - __half2float(h));
}
__device__ __forceinline__ uint32_t pack2(__half a, __half b) {
    return (uint32_t)__half_as_ushort(a) | ((uint32_t)__half_as_ushort(b) << 16);
}
#define CP_ASYNC16(dst, src) asm volatile("cp.async.cg.shared.global [%0], [%1], 16;" :: "r"(dst), "l"(src))
#define CP_COMMIT() asm volatile("cp.async.commit_group;" ::: "memory")
#define CP_WAIT0()  asm volatile("cp.async.wait_group 0;" ::: "memory")
#define CP_WAIT1()  asm volatile("cp.async.wait_group 1;" ::: "memory")

__global__ void __launch_bounds__(256) split_f32_kernel(
    const float* __restrict__ in, __half* __restrict__ h,
    __half* __restrict__ l, int n4)
{
    int i = blockIdx.x * 256 + threadIdx.x;
    if (i >= n4) return;
    float4 v = ((const float4*)in)[i];
    __half h0,l0,h1,l1,h2,l2,h3,l3;
    split_h(v.x,h0,l0); split_h(v.y,h1,l1);
    split_h(v.z,h2,l2); split_h(v.w,h3,l3);
    ((uint2*)h)[i] = make_uint2(pack2(h0,h1), pack2(h2,h3));
    ((uint2*)l)[i] = make_uint2(pack2(l0,l1), pack2(l2,l3));
}

__global__ void __launch_bounds__(256) split_weights_kernel(
    const float* __restrict__ Wq, const float* __restrict__ Wk,
    __half* __restrict__ wq0, __half* __restrict__ wq1,
    __half* __restrict__ wk0, __half* __restrict__ wk1)
{
    int i = blockIdx.x * 256 + threadIdx.x;
    const int NW = D_ * F_;
    if (i >= 2 * NW) return;
    int which = i / NW, j = i - which * NW;
    int n = j / D_, k = j - n * D_;
    __half h, l;
    split_h((which == 0 ? Wq : Wk)[(size_t)k * F_ + n], h, l);
    (which == 0 ? wq0 : wk0)[j] = h;
    (which == 0 ? wq1 : wk1)[j] = l;
}

// W2 = Wv @ Wfc (fp32 -> fp16 split, transposed); c2 = bv@Wfc + bfc.
// 257 blocks: 0..255 do 2 k-rows each, block 256 does c2.
__global__ void __launch_bounds__(256) w2c2_kernel(
    const float* __restrict__ Wv, const float* __restrict__ Wfc,
    const float* __restrict__ bv, const float* __restrict__ bfc,
    __half* __restrict__ w2h, __half* __restrict__ w2l, float* __restrict__ c2)
{
    const int n = threadIdx.x;
    const int kb = blockIdx.x;
    if (kb == 256) {
        float s = bfc[n];
        for (int j = 0; j < F_; j++) s += bv[j] * Wfc[(size_t)j * F_ + n];
        c2[n] = s;
        return;
    }
    __shared__ float wv[2][F_];
    wv[0][n] = Wv[(size_t)(kb * 2 + 0) * F_ + n];
    wv[1][n] = Wv[(size_t)(kb * 2 + 1) * F_ + n];
    __syncthreads();
    float s0 = 0.f, s1 = 0.f;
    for (int j = 0; j < F_; j++) {
        float wf = Wfc[(size_t)j * F_ + n];
        s0 += wv[0][j] * wf;
        s1 += wv[1][j] * wf;
    }
    __half h, l;
    split_h(s0, h, l);
    size_t i0 = (size_t)n * D_ + kb * 2;
    w2h[i0] = h; w2l[i0] = l;
    split_h(s1, h, l);
    w2h[i0 + 1] = h; w2l[i0 + 1] = l;
}

// ---------------------------------------------------------------------------
// Shared HMMA GEMM body: CTA 128x128, 8 warps (2m x 4n), warp 64x32,
// k-block 32, 3-stage cp.async (96KB), packed hi|lo 128B rows.
// NCH = 3: A hi+lo, chains AhBh+AhBl+AlBh. NCH = 2: A plain, chains ABh+ABl.
// ---------------------------------------------------------------------------
#define GEMM_SMEM 98304

#define GEMM_PROLOG \
    extern __shared__ char sm[]; \
    const uint32_t smb = smem_to_u32(sm); \
    const int tid = threadIdx.x, lane = tid & 31, wid = tid >> 5; \
    const int wm = wid & 1, wn = wid >> 1; \
    const int arow = wm * 64 + (lane & 15); \
    const int as = arow & 7, ah = lane >> 4; \
    const int brow = wn * 32 + ((lane >> 4) << 3) + (lane & 7); \
    const int bs = lane & 7, bh2 = (lane >> 3) & 1; \
    const int lq = lane & 3;

#define GISSUE(buf, k0, KDV, NCH) do { \
    uint32_t gb = smb + (buf) * 32768; \
    _Pragma("unroll") \
    for (int p = 0; p < 4; p++) { \
        int id = p * 256 + tid; int r = id >> 3, c = id & 7; \
        uint32_t d = r * 128 + (((uint32_t)(c ^ (r & 7))) << 4); \
        if ((NCH) == 3 || c < 4) { \
            const __half* sa = (c < 4) ? Ah + (size_t)(ma + r) * (KDV) + (k0) + c * 8 \
                                       : Al + (size_t)(ma + r) * (KDV) + (k0) + (c - 4) * 8; \
            CP_ASYNC16(gb + d, sa); \
        } \
        const __half* sb = (c < 4) ? Bh + (size_t)(nb + r) * (KDV) + (k0) + c * 8 \
                                   : Bl + (size_t)(nb + r) * (KDV) + (k0) + (c - 4) * 8; \
        CP_ASYNC16(gb + 16384 + d, sb); \
    } } while (0)

#define GEMM_MAIN(KDV, NCH) \
    float acc[4][4][4]; \
    _Pragma("unroll") \
    for (int i = 0; i < 4; i++) \
        _Pragma("unroll") \
        for (int j = 0; j < 4; j++) \
            _Pragma("unroll") \
            for (int k = 0; k < 4; k++) acc[i][j][k] = 0.f; \
    { \
        const int T = (KDV) / 32; \
        GISSUE(0, 0, KDV, NCH); CP_COMMIT(); \
        if (T > 1) { GISSUE(1, 32, KDV, NCH); CP_COMMIT(); } \
        for (int t = 0; t < T; t++) { \
            if (t + 1 < T) { CP_WAIT1(); } else { CP_WAIT0(); } \
            __syncthreads(); \
            if (t + 2 < T) { GISSUE((t + 2) % 3, (t + 2) * 32, KDV, NCH); CP_COMMIT(); } \
            const int cur = t % 3; \
            uint32_t aP = smb + cur * 32768 + arow * 128; \
            uint32_t bP = smb + cur * 32768 + 16384 + brow * 128; \
            _Pragma("unroll") \
            for (int ks = 0; ks < 2; ks++) { \
                uint32_t hcA = (uint32_t)(2 * ks + ah); \
                uint32_t aq[4][4], alr[4][4]; \
                _Pragma("unroll") \
                for (int mi = 0; mi < 4; mi++) { \
                    ldsm4(aq[mi], aP + mi * 2048 + ((hcA ^ (uint32_t)as) << 4)); \
                    if ((NCH) == 3) \
                        ldsm4(alr[mi], aP + mi * 2048 + (((hcA + 4) ^ (uint32_t)as) << 4)); \
                } \
                uint32_t hcB = (uint32_t)(2 * ks + bh2); \
                _Pragma("unroll") \
                for (int ni = 0; ni < 2; ni++) { \
                    uint32_t bhh[4], bll[4]; \
                    ldsm4(bhh, bP + ni * 2048 + ((hcB ^ (uint32_t)bs) << 4)); \
                    ldsm4(bll, bP + ni * 2048 + (((hcB + 4) ^ (uint32_t)bs) << 4)); \
                    _Pragma("unroll") \
                    for (int mi = 0; mi < 4; mi++) { \
                        mma_f16(acc[mi][2*ni],   aq[mi], bhh[0], bhh[1]); \
                        mma_f16(acc[mi][2*ni],   aq[mi], bll[0], bll[1]); \
                        mma_f16(acc[mi][2*ni+1], aq[mi], bhh[2], bhh[3]); \
                        mma_f16(acc[mi][2*ni+1], aq[mi], bll[2], bll[3]); \
                        if ((NCH) == 3) { \
                            mma_f16(acc[mi][2*ni],   alr[mi], bhh[0], bhh[1]); \
                            mma_f16(acc[mi][2*ni+1], alr[mi], bhh[2], bhh[3]); \
                        } \
                    } \
                } \
            } \
        } \
        __syncthreads(); \
    }

// ---------------------------------------------------------------------------
// Fused Q/K/V' projections: z=0 Q (plain fp16 out), z=1 K (split), z=2 V'T (split).
// ---------------------------------------------------------------------------
__global__ void __launch_bounds__(256, 2) gemm_qkv(
    const __half* __restrict__ f1h, const __half* __restrict__ f1l,
    const __half* __restrict__ f2h, const __half* __restrict__ f2l,
    const __half* __restrict__ wqh, const __half* __restrict__ wql,
    const __half* __restrict__ wkh, const __half* __restrict__ wkl,
    const __half* __restrict__ w2h, const __half* __restrict__ w2l,
    const float* __restrict__ bq, const float* __restrict__ bk, const float* __restrict__ bz,
    __half* __restrict__ Q,
    __half* __restrict__ Kh, __half* __restrict__ Kl,
    __half* __restrict__ VTh, __half* __restrict__ VTl)
{
    GEMM_PROLOG
    const int n0 = blockIdx.x * 128, m0 = blockIdx.y * 128;
    const int z = blockIdx.z;
    const int ma = m0, nb = n0;
    const __half* Ah = z == 0 ? f1h : f2h;
    const __half* Al = z == 0 ? f1l : f2l;
    const __half* Bh = z == 0 ? wqh : (z == 1 ? wkh : w2h);
    const __half* Bl = z == 0 ? wql : (z == 1 ? wkl : w2l);
    const float* bias = z == 0 ? bq : (z == 1 ? bk : bz);

    GEMM_MAIN(D_, 3)

    #pragma unroll
    for (int mi = 0; mi < 4; mi++) {
        int r0 = m0 + wm * 64 + mi * 16 + (lane >> 2);
        int r1 = r0 + 8;
        #pragma unroll
        for (int nt = 0; nt < 4; nt++) {
            int col = n0 + wn * 32 + nt * 8 + 2 * lq;
            float b0 = bias[col], b1 = bias[col + 1];
            float v0 = acc[mi][nt][0] + b0, v1 = acc[mi][nt][1] + b1;
            float v2 = acc[mi][nt][2] + b0, v3 = acc[mi][nt][3] + b1;
            if (z == 0) {
                size_t o0 = (size_t)r0 * 256 + col, o1 = (size_t)r1 * 256 + col;
                *(uint32_t*)(Q + o0) = pack2(__float2half_rn(v0), __float2half_rn(v1));
                *(uint32_t*)(Q + o1) = pack2(__float2half_rn(v2), __float2half_rn(v3));
            } else {
                __half h0,l0,h1,l1,h2,l2,h3,l3;
                split_h(v0,h0,l0); split_h(v1,h1,l1);
                split_h(v2,h2,l2); split_h(v3,h3,l3);
                if (z == 1) {
                    size_t o0 = (size_t)r0 * 256 + col, o1 = (size_t)r1 * 256 + col;
                    *(uint32_t*)(Kh + o0) = pack2(h0, h1);
                    *(uint32_t*)(Kl + o0) = pack2(l0, l1);
                    *(uint32_t*)(Kh + o1) = pack2(h2, h3);
                    *(uint32_t*)(Kl + o1) = pack2(l2, l3);
                } else {
                    size_t o0 = (size_t)(r0 >> 11) * (F_ * S2_) + (size_t)col * S2_ + (r0 & 2047);
                    size_t o1 = (size_t)(r1 >> 11) * (F_ * S2_) + (size_t)col * S2_ + (r1 & 2047);
                    VTh[o0] = h0; VTh[o0 + S2_] = h1; VTl[o0] = l0; VTl[o0 + S2_] = l1;
                    VTh[o1] = h2; VTh[o1 + S2_] = h3; VTl[o1] = l2; VTl[o1 + S2_] = l3;
                }
            }
        }
    }
}

// ---------------------------------------------------------------------------
// S-kernel: P = exp(scale * Q@K^T) plain fp16 + per-128-block row sums. 2-chain.
// ---------------------------------------------------------------------------
__global__ void __launch_bounds__(256, 2) gemm_S(
    const __half* __restrict__ Q,
    const __half* __restrict__ Kh, const __half* __restrict__ Kl,
    __half* __restrict__ P, float* __restrict__ lp)
{
    GEMM_PROLOG
    const int kblk = blockIdx.x, qblk = blockIdx.y, b = blockIdx.z;
    const int ma = qblk * 128, nb = kblk * 128;
    const __half* Ah = Q + (size_t)b * S1_ * F_;
    const __half* Al = Ah;                      // unused (NCH=2)
    const __half* Bh = Kh + (size_t)b * S2_ * F_;
    const __half* Bl = Kl + (size_t)b * S2_ * F_;

    GEMM_MAIN(F_, 2)

    const float scale = 0.0625f;
    const int bq0 = b * S1_ + qblk * 128;
    const int kb0 = kblk * 128;
    float rsum[4][2];
    #pragma unroll
    for (int mi = 0; mi < 4; mi++) { rsum[mi][0] = 0.f; rsum[mi][1] = 0.f; }

    #pragma unroll
    for (int mi = 0; mi < 4; mi++) {
        int rl0 = wm * 64 + mi * 16 + (lane >> 2);
        size_t pb0 = (size_t)(bq0 + rl0) * S2_ + kb0;
        size_t pb1 = (size_t)(bq0 + rl0 + 8) * S2_ + kb0;
        #pragma unroll
        for (int nt = 0; nt < 4; nt++) {
            int col = wn * 32 + nt * 8 + 2 * lq;
            float p0 = __expf(acc[mi][nt][0] * scale);
            float p1 = __expf(acc[mi][nt][1] * scale);
            float p2 = __expf(acc[mi][nt][2] * scale);
            float p3 = __expf(acc[mi][nt][3] * scale);
            rsum[mi][0] += p0 + p1;
            rsum[mi][1] += p2 + p3;
            *(uint32_t*)(P + pb0 + col) = pack2(__float2half_rn(p0), __float2half_rn(p1));
            *(uint32_t*)(P + pb1 + col) = pack2(__float2half_rn(p2), __float2half_rn(p3));
        }
    }
    #pragma unroll
    for (int mi = 0; mi < 4; mi++) {
        #pragma unroll
        for (int u = 0; u < 2; u++) {
            rsum[mi][u] += __shfl_xor_sync(0xffffffffu, rsum[mi][u], 1);
            rsum[mi][u] += __shfl_xor_sync(0xffffffffu, rsum[mi][u], 2);
        }
    }
    float* red = (float*)sm;
    __syncthreads();
    if (lq == 0) {
        #pragma unroll
        for (int mi = 0; mi < 4; mi++) {
            int rl = wm * 64 + mi * 16 + (lane >> 2);
            red[wn * 128 + rl]     = rsum[mi][0];
            red[wn * 128 + rl + 8] = rsum[mi][1];
        }
    }
    __syncthreads();
    if (tid < 128)
        lp[(size_t)(bq0 + tid) * 16 + kblk] =
            (red[tid] + red[128 + tid]) + (red[256 + tid] + red[384 + tid]);
}

__global__ void __launch_bounds__(256) lreduce_kernel(const float* __restrict__ lp,
                                                      float* __restrict__ l)
{
    int i = blockIdx.x * 256 + threadIdx.x;
    if (i >= B_ * S1_) return;
    float s = 0.f;
    #pragma unroll
    for (int j = 0; j < 16; j++) s += lp[(size_t)i * 16 + j];
    l[i] = s;
}

// ---------------------------------------------------------------------------
// PV-kernel: out = (P@VT'^T)/l + c2 (final fp32 output). 2-chain.
// ---------------------------------------------------------------------------
__global__ void __launch_bounds__(256, 2) gemm_pv(
    const __half* __restrict__ P,
    const __half* __restrict__ VTh, const __half* __restrict__ VTl,
    const float* __restrict__ l, const float* __restrict__ c2,
    float* __restrict__ out)
{
    GEMM_PROLOG
    const int fblk = blockIdx.x, qblk = blockIdx.y, b = blockIdx.z;
    const int ma = qblk * 128, nb = fblk * 128;
    const __half* Ah = P + (size_t)b * S1_ * S2_;
    const __half* Al = Ah;                      // unused (NCH=2)
    const __half* Bh = VTh + (size_t)b * F_ * S2_;
    const __half* Bl = VTl + (size_t)b * F_ * S2_;

    GEMM_MAIN(S2_, 2)

    const int bq0 = b * S1_ + qblk * 128;
    #pragma unroll
    for (int mi = 0; mi < 4; mi++) {
        int rl0 = wm * 64 + mi * 16 + (lane >> 2);
        float inv0 = 1.f / l[bq0 + rl0];
        float inv1 = 1.f / l[bq0 + rl0 + 8];
        size_t o0 = (size_t)(bq0 + rl0) * 256;
        size_t o1 = (size_t)(bq0 + rl0 + 8) * 256;
        #pragma unroll
        for (int nt = 0; nt < 4; nt++) {
            int col = fblk * 128 + wn * 32 + nt * 8 + 2 * lq;
            float c0 = c2[col], c1 = c2[col + 1];
            *(float2*)(out + o0 + col) =
                make_float2(acc[mi][nt][0] * inv0 + c0, acc[mi][nt][1] * inv0 + c1);
            *(float2*)(out + o1 + col) =
                make_float2(acc[mi][nt][2] * inv1 + c0, acc[mi][nt][3] * inv1 + c1);
        }
    }
}

// ---------------------------------------------------------------------------
extern "C" void kernel_launch(void* const* d_in, const int* in_sizes, int n_in,
                              void* d_out, int out_size)
{
    const float* feat1 = (const float*)d_in[0];
    const float* feat2 = (const float*)d_in[1];
    const float* Wq    = (const float*)d_in[2];
    const float* bq    = (const float*)d_in[3];
    const float* Wk    = (const float*)d_in[4];
    const float* bk    = (const float*)d_in[5];
    const float* Wv    = (const float*)d_in[6];
    const float* bv    = (const float*)d_in[7];
    const float* Wfc   = (const float*)d_in[8];
    const float* bfc   = (const float*)d_in[9];
    float* out = (float*)d_out;

    __half *f1h, *f1l, *f2h, *f2l, *Q, *Kh, *Kl, *VTh, *VTl, *P;
    float *lp, *lv, *c2, *zv;
    __half (*wq)[D_ * F_]; __half (*wk)[D_ * F_]; __half (*w2)[D_ * F_];
    cudaGetSymbolAddress((void**)&f1h, g_f1h);
    cudaGetSymbolAddress((void**)&f1l, g_f1l);
    cudaGetSymbolAddress((void**)&f2h, g_f2h);
    cudaGetSymbolAddress((void**)&f2l, g_f2l);
    cudaGetSymbolAddress((void**)&wq,  g_wq);
    cudaGetSymbolAddress((void**)&wk,  g_wk);
    cudaGetSymbolAddress((void**)&w2,  g_w2);
    cudaGetSymbolAddress((void**)&c2,  g_c2);
    cudaGetSymbolAddress((void**)&zv,  g_zero);
    cudaGetSymbolAddress((void**)&Q,   g_Q);
    cudaGetSymbolAddress((void**)&Kh,  g_Kh);
    cudaGetSymbolAddress((void**)&Kl,  g_Kl);
    cudaGetSymbolAddress((void**)&VTh, g_VTh);
    cudaGetSymbolAddress((void**)&VTl, g_VTl);
    cudaGetSymbolAddress((void**)&P,   g_P);
    cudaGetSymbolAddress((void**)&lp,  g_lp);
    cudaGetSymbolAddress((void**)&lv,  g_l);

    split_f32_kernel<<<NFEAT / 4 / 256, 256>>>(feat1, f1h, f1l, NFEAT / 4);
    split_f32_kernel<<<NFEAT / 4 / 256, 256>>>(feat2, f2h, f2l, NFEAT / 4);
    split_weights_kernel<<<(2 * D_ * F_ + 255) / 256, 256>>>(Wq, Wk, wq[0], wq[1], wk[0], wk[1]);
    w2c2_kernel<<<257, 256>>>(Wv, Wfc, bv, bfc, w2[0], w2[1], c2);

    cudaFuncSetAttribute(gemm_qkv, cudaFuncAttributeMaxDynamicSharedMemorySize, GEMM_SMEM);
    cudaFuncSetAttribute(gemm_S,   cudaFuncAttributeMaxDynamicSharedMemorySize, GEMM_SMEM);
    cudaFuncSetAttribute(gemm_pv,  cudaFuncAttributeMaxDynamicSharedMemorySize, GEMM_SMEM);

    dim3 gq(2, B_ * S1_ / 128, 3);
    gemm_qkv<<<gq, 256, GEMM_SMEM>>>(f1h, f1l, f2h, f2l,
                                     wq[0], wq[1], wk[0], wk[1], w2[0], w2[1],
                                     bq, bk, zv, Q, Kh, Kl, VTh, VTl);

    dim3 gs(S2_ / 128, S1_ / 128, B_);
    gemm_S<<<gs, 256, GEMM_SMEM>>>(Q, Kh, Kl, P, lp);

    lreduce_kernel<<<(B_ * S1_ + 255) / 256, 256>>>(lp, lv);

    dim3 gp(F_ / 128, S1_ / 128, B_);
    gemm_pv<<<gp, 256, GEMM_SMEM>>>(P, VTh, VTl, lv, c2, out);
}

// round 14
// speedup vs baseline: 1.7330x; 1.2911x over previous
#include <cuda_runtime.h>
#include <cuda_fp16.h>
#include <cstdint>

#define B_  8
#define S1_ 2048
#define S2_ 2048
#define D_  512
#define F_  256
#define NQKV (B_ * S1_ * F_)
#define NFEAT (B_ * S1_ * D_)
#define NP   (B_ * S1_ * S2_)

__device__ __align__(16) __half g_f1h[NFEAT];
__device__ __align__(16) __half g_f1l[NFEAT];
__device__ __align__(16) __half g_f2h[NFEAT];
__device__ __align__(16) __half g_f2l[NFEAT];
__device__ __align__(16) __half g_wq[2][D_ * F_];
__device__ __align__(16) __half g_wk[2][D_ * F_];
__device__ __align__(16) __half g_w2[2][D_ * F_];   // (Wv@Wfc)^T split
__device__ __align__(16) float  g_c2[F_];           // bv@Wfc + bfc
__device__ __align__(16) float  g_zero[F_];
__device__ __align__(16) __half g_Q  [NQKV];        // plain fp16
__device__ __align__(16) __half g_K  [NQKV];        // plain fp16
__device__ __align__(16) __half g_VT [NQKV];        // [b, f, t], plain fp16
__device__ __align__(16) __half g_P  [NP];          // plain fp16
__device__ __align__(16) float  g_lp [B_ * S1_ * 16];
__device__ __align__(16) float  g_l  [B_ * S1_];

__device__ __forceinline__ uint32_t smem_to_u32(const void* p) {
    uint32_t a;
    asm("{ .reg .u64 t; cvta.to.shared.u64 t, %1; cvt.u32.u64 %0, t; }" : "=r"(a) : "l"(p));
    return a;
}
__device__ __forceinline__ void ldsm4(uint32_t* r, uint32_t a) {
    asm volatile("ldmatrix.sync.aligned.m8n8.x4.shared.b16 {%0,%1,%2,%3}, [%4];"
        : "=r"(r[0]), "=r"(r[1]), "=r"(r[2]), "=r"(r[3]) : "r"(a));
}
__device__ __forceinline__ void mma_f16(float (&d)[4], const uint32_t* a, uint32_t b0, uint32_t b1) {
    asm volatile("mma.sync.aligned.m16n8k16.row.col.f32.f16.f16.f32 "
        "{%0,%1,%2,%3}, {%4,%5,%6,%7}, {%8,%9}, {%0,%1,%2,%3};"
        : "+f"(d[0]), "+f"(d[1]), "+f"(d[2]), "+f"(d[3])
        : "r"(a[0]), "r"(a[1]), "r"(a[2]), "r"(a[3]), "r"(b0), "r"(b1));
}
__device__ __forceinline__ void split_h(float x, __half& h, __half& l) {
    h = __float2half_rn(x);
    l = __float2half_rn(x - __half2float(h));
}
__device__ __forceinline__ uint32_t pack2(__half a, __half b) {
    return (uint32_t)__half_as_ushort(a) | ((uint32_t)__half_as_ushort(b) << 16);
}
#define CP_ASYNC16(dst, src) asm volatile("cp.async.cg.shared.global [%0], [%1], 16;" :: "r"(dst), "l"(src))
#define CP_COMMIT() asm volatile("cp.async.commit_group;" ::: "memory")
#define CP_WAIT0()  asm volatile("cp.async.wait_group 0;" ::: "memory")
#define CP_WAIT1()  asm volatile("cp.async.wait_group 1;" ::: "memory")

__global__ void __launch_bounds__(256) split_f32_kernel(
    const float* __restrict__ in, __half* __restrict__ h,
    __half* __restrict__ l, int n4)
{
    int i = blockIdx.x * 256 + threadIdx.x;
    if (i >= n4) return;
    float4 v = ((const float4*)in)[i];
    __half h0,l0,h1,l1,h2,l2,h3,l3;
    split_h(v.x,h0,l0); split_h(v.y,h1,l1);
    split_h(v.z,h2,l2); split_h(v.w,h3,l3);
    ((uint2*)h)[i] = make_uint2(pack2(h0,h1), pack2(h2,h3));
    ((uint2*)l)[i] = make_uint2(pack2(l0,l1), pack2(l2,l3));
}

__global__ void __launch_bounds__(256) split_weights_kernel(
    const float* __restrict__ Wq, const float* __restrict__ Wk,
    __half* __restrict__ wq0, __half* __restrict__ wq1,
    __half* __restrict__ wk0, __half* __restrict__ wk1)
{
    int i = blockIdx.x * 256 + threadIdx.x;
    const int NW = D_ * F_;
    if (i >= 2 * NW) return;
    int which = i / NW, j = i - which * NW;
    int n = j / D_, k = j - n * D_;
    __half h, l;
    split_h((which == 0 ? Wq : Wk)[(size_t)k * F_ + n], h, l);
    (which == 0 ? wq0 : wk0)[j] = h;
    (which == 0 ? wq1 : wk1)[j] = l;
}

// W2 = Wv @ Wfc (fp32 -> fp16 split, transposed); c2 = bv@Wfc + bfc.
__global__ void __launch_bounds__(256) w2c2_kernel(
    const float* __restrict__ Wv, const float* __restrict__ Wfc,
    const float* __restrict__ bv, const float* __restrict__ bfc,
    __half* __restrict__ w2h, __half* __restrict__ w2l, float* __restrict__ c2)
{
    const int n = threadIdx.x;
    const int kb = blockIdx.x;
    if (kb == 256) {
        float s = bfc[n];
        for (int j = 0; j < F_; j++) s += bv[j] * Wfc[(size_t)j * F_ + n];
        c2[n] = s;
        return;
    }
    __shared__ float wv[2][F_];
    wv[0][n] = Wv[(size_t)(kb * 2 + 0) * F_ + n];
    wv[1][n] = Wv[(size_t)(kb * 2 + 1) * F_ + n];
    __syncthreads();
    float s0 = 0.f, s1 = 0.f;
    for (int j = 0; j < F_; j++) {
        float wf = Wfc[(size_t)j * F_ + n];
        s0 += wv[0][j] * wf;
        s1 += wv[1][j] * wf;
    }
    __half h, l;
    split_h(s0, h, l);
    size_t i0 = (size_t)n * D_ + kb * 2;
    w2h[i0] = h; w2l[i0] = l;
    split_h(s1, h, l);
    w2h[i0 + 1] = h; w2l[i0 + 1] = l;
}

// ---------------------------------------------------------------------------
// Shared HMMA GEMM body: CTA 128x128, 8 warps (2m x 4n), warp 64x32,
// k-block 32, 3-stage cp.async (96KB), packed hi|lo 128B rows.
// NCH = 3: A split, B split, chains AhBh+AhBl+AlBh.
// NCH = 1: A plain, B plain (hi chunks only), single chain.
// ---------------------------------------------------------------------------
#define GEMM_SMEM 98304

#define GEMM_PROLOG \
    extern __shared__ char sm[]; \
    const uint32_t smb = smem_to_u32(sm); \
    const int tid = threadIdx.x, lane = tid & 31, wid = tid >> 5; \
    const int wm = wid & 1, wn = wid >> 1; \
    const int arow = wm * 64 + (lane & 15); \
    const int as = arow & 7, ah = lane >> 4; \
    const int brow = wn * 32 + ((lane >> 4) << 3) + (lane & 7); \
    const int bs = lane & 7, bh2 = (lane >> 3) & 1; \
    const int lq = lane & 3;

#define GISSUE(buf, k0, KDV, NCH) do { \
    uint32_t gb = smb + (buf) * 32768; \
    _Pragma("unroll") \
    for (int p = 0; p < 4; p++) { \
        int id = p * 256 + tid; int r = id >> 3, c = id & 7; \
        uint32_t d = r * 128 + (((uint32_t)(c ^ (r & 7))) << 4); \
        if ((NCH) == 3 || c < 4) { \
            const __half* sa = (c < 4) ? Ah + (size_t)(ma + r) * (KDV) + (k0) + c * 8 \
                                       : Al + (size_t)(ma + r) * (KDV) + (k0) + (c - 4) * 8; \
            CP_ASYNC16(gb + d, sa); \
            const __half* sb = (c < 4) ? Bh + (size_t)(nb + r) * (KDV) + (k0) + c * 8 \
                                       : Bl + (size_t)(nb + r) * (KDV) + (k0) + (c - 4) * 8; \
            CP_ASYNC16(gb + 16384 + d, sb); \
        } \
    } } while (0)

#define GEMM_MAIN(KDV, NCH) \
    float acc[4][4][4]; \
    _Pragma("unroll") \
    for (int i = 0; i < 4; i++) \
        _Pragma("unroll") \
        for (int j = 0; j < 4; j++) \
            _Pragma("unroll") \
            for (int k = 0; k < 4; k++) acc[i][j][k] = 0.f; \
    { \
        const int T = (KDV) / 32; \
        GISSUE(0, 0, KDV, NCH); CP_COMMIT(); \
        if (T > 1) { GISSUE(1, 32, KDV, NCH); CP_COMMIT(); } \
        for (int t = 0; t < T; t++) { \
            if (t + 1 < T) { CP_WAIT1(); } else { CP_WAIT0(); } \
            __syncthreads(); \
            if (t + 2 < T) { GISSUE((t + 2) % 3, (t + 2) * 32, KDV, NCH); CP_COMMIT(); } \
            const int cur = t % 3; \
            uint32_t aP = smb + cur * 32768 + arow * 128; \
            uint32_t bP = smb + cur * 32768 + 16384 + brow * 128; \
            _Pragma("unroll") \
            for (int ks = 0; ks < 2; ks++) { \
                uint32_t hcA = (uint32_t)(2 * ks + ah); \
                uint32_t aq[4][4], alr[4][4]; \
                _Pragma("unroll") \
                for (int mi = 0; mi < 4; mi++) { \
                    ldsm4(aq[mi], aP + mi * 2048 + ((hcA ^ (uint32_t)as) << 4)); \
                    if ((NCH) == 3) \
                        ldsm4(alr[mi], aP + mi * 2048 + (((hcA + 4) ^ (uint32_t)as) << 4)); \
                } \
                uint32_t hcB = (uint32_t)(2 * ks + bh2); \
                _Pragma("unroll") \
                for (int ni = 0; ni < 2; ni++) { \
                    uint32_t bhh[4], bll[4]; \
                    ldsm4(bhh, bP + ni * 2048 + ((hcB ^ (uint32_t)bs) << 4)); \
                    if ((NCH) == 3) \
                        ldsm4(bll, bP + ni * 2048 + (((hcB + 4) ^ (uint32_t)bs) << 4)); \
                    _Pragma("unroll") \
                    for (int mi = 0; mi < 4; mi++) { \
                        mma_f16(acc[mi][2*ni],   aq[mi], bhh[0], bhh[1]); \
                        mma_f16(acc[mi][2*ni+1], aq[mi], bhh[2], bhh[3]); \
                        if ((NCH) == 3) { \
                            mma_f16(acc[mi][2*ni],   aq[mi],  bll[0], bll[1]); \
                            mma_f16(acc[mi][2*ni],   alr[mi], bhh[0], bhh[1]); \
                            mma_f16(acc[mi][2*ni+1], aq[mi],  bll[2], bll[3]); \
                            mma_f16(acc[mi][2*ni+1], alr[mi], bhh[2], bhh[3]); \
                        } \
                    } \
                } \
            } \
        } \
        __syncthreads(); \
    }

// ---------------------------------------------------------------------------
// Fused Q/K/V' projections: all plain fp16 out. z=2 writes transposed VT.
// ---------------------------------------------------------------------------
__global__ void __launch_bounds__(256, 2) gemm_qkv(
    const __half* __restrict__ f1h, const __half* __restrict__ f1l,
    const __half* __restrict__ f2h, const __half* __restrict__ f2l,
    const __half* __restrict__ wqh, const __half* __restrict__ wql,
    const __half* __restrict__ wkh, const __half* __restrict__ wkl,
    const __half* __restrict__ w2h, const __half* __restrict__ w2l,
    const float* __restrict__ bq, const float* __restrict__ bk, const float* __restrict__ bz,
    __half* __restrict__ Q, __half* __restrict__ K, __half* __restrict__ VT)
{
    GEMM_PROLOG
    const int n0 = blockIdx.x * 128, m0 = blockIdx.y * 128;
    const int z = blockIdx.z;
    const int ma = m0, nb = n0;
    const __half* Ah = z == 0 ? f1h : f2h;
    const __half* Al = z == 0 ? f1l : f2l;
    const __half* Bh = z == 0 ? wqh : (z == 1 ? wkh : w2h);
    const __half* Bl = z == 0 ? wql : (z == 1 ? wkl : w2l);
    const float* bias = z == 0 ? bq : (z == 1 ? bk : bz);
    __half* O = z == 0 ? Q : (z == 1 ? K : VT);

    GEMM_MAIN(D_, 3)

    #pragma unroll
    for (int mi = 0; mi < 4; mi++) {
        int r0 = m0 + wm * 64 + mi * 16 + (lane >> 2);
        int r1 = r0 + 8;
        #pragma unroll
        for (int nt = 0; nt < 4; nt++) {
            int col = n0 + wn * 32 + nt * 8 + 2 * lq;
            float b0 = bias[col], b1 = bias[col + 1];
            __half h0 = __float2half_rn(acc[mi][nt][0] + b0);
            __half h1 = __float2half_rn(acc[mi][nt][1] + b1);
            __half h2 = __float2half_rn(acc[mi][nt][2] + b0);
            __half h3 = __float2half_rn(acc[mi][nt][3] + b1);
            if (z < 2) {
                *(uint32_t*)(O + (size_t)r0 * 256 + col) = pack2(h0, h1);
                *(uint32_t*)(O + (size_t)r1 * 256 + col) = pack2(h2, h3);
            } else {
                size_t o0 = (size_t)(r0 >> 11) * (F_ * S2_) + (size_t)col * S2_ + (r0 & 2047);
                size_t o1 = (size_t)(r1 >> 11) * (F_ * S2_) + (size_t)col * S2_ + (r1 & 2047);
                O[o0] = h0; O[o0 + S2_] = h1;
                O[o1] = h2; O[o1 + S2_] = h3;
            }
        }
    }
}

// ---------------------------------------------------------------------------
// S-kernel: P = exp(scale * Q@K^T) fp16 + per-128-block row sums. 1 chain.
// ---------------------------------------------------------------------------
__global__ void __launch_bounds__(256, 2) gemm_S(
    const __half* __restrict__ Q, const __half* __restrict__ K,
    __half* __restrict__ P, float* __restrict__ lp)
{
    GEMM_PROLOG
    const int kblk = blockIdx.x, qblk = blockIdx.y, b = blockIdx.z;
    const int ma = qblk * 128, nb = kblk * 128;
    const __half* Ah = Q + (size_t)b * S1_ * F_;
    const __half* Al = Ah;   // unused
    const __half* Bh = K + (size_t)b * S2_ * F_;
    const __half* Bl = Bh;   // unused

    GEMM_MAIN(F_, 1)

    const float scale = 0.0625f;
    const int bq0 = b * S1_ + qblk * 128;
    const int kb0 = kblk * 128;
    float rsum[4][2];
    #pragma unroll
    for (int mi = 0; mi < 4; mi++) { rsum[mi][0] = 0.f; rsum[mi][1] = 0.f; }

    #pragma unroll
    for (int mi = 0; mi < 4; mi++) {
        int rl0 = wm * 64 + mi * 16 + (lane >> 2);
        size_t pb0 = (size_t)(bq0 + rl0) * S2_ + kb0;
        size_t pb1 = (size_t)(bq0 + rl0 + 8) * S2_ + kb0;
        #pragma unroll
        for (int nt = 0; nt < 4; nt++) {
            int col = wn * 32 + nt * 8 + 2 * lq;
            float p0 = __expf(acc[mi][nt][0] * scale);
            float p1 = __expf(acc[mi][nt][1] * scale);
            float p2 = __expf(acc[mi][nt][2] * scale);
            float p3 = __expf(acc[mi][nt][3] * scale);
            rsum[mi][0] += p0 + p1;
            rsum[mi][1] += p2 + p3;
            *(uint32_t*)(P + pb0 + col) = pack2(__float2half_rn(p0), __float2half_rn(p1));
            *(uint32_t*)(P + pb1 + col) = pack2(__float2half_rn(p2), __float2half_rn(p3));
        }
    }
    #pragma unroll
    for (int mi = 0; mi < 4; mi++) {
        #pragma unroll
        for (int u = 0; u < 2; u++) {
            rsum[mi][u] += __shfl_xor_sync(0xffffffffu, rsum[mi][u], 1);
            rsum[mi][u] += __shfl_xor_sync(0xffffffffu, rsum[mi][u], 2);
        }
    }
    float* red = (float*)sm;
    __syncthreads();
    if (lq == 0) {
        #pragma unroll
        for (int mi = 0; mi < 4; mi++) {
            int rl = wm * 64 + mi * 16 + (lane >> 2);
            red[wn * 128 + rl]     = rsum[mi][0];
            red[wn * 128 + rl + 8] = rsum[mi][1];
        }
    }
    __syncthreads();
    if (tid < 128)
        lp[(size_t)(bq0 + tid) * 16 + kblk] =
            (red[tid] + red[128 + tid]) + (red[256 + tid] + red[384 + tid]);
}

__global__ void __launch_bounds__(256) lreduce_kernel(const float* __restrict__ lp,
                                                      float* __restrict__ l)
{
    int i = blockIdx.x * 256 + threadIdx.x;
    if (i >= B_ * S1_) return;
    float s = 0.f;
    #pragma unroll
    for (int j = 0; j < 16; j++) s += lp[(size_t)i * 16 + j];
    l[i] = s;
}

// ---------------------------------------------------------------------------
// PV-kernel: out = (P@VT^T)/l + c2 (final fp32 output). 1 chain.
// ---------------------------------------------------------------------------
__global__ void __launch_bounds__(256, 2) gemm_pv(
    const __half* __restrict__ P, const __half* __restrict__ VT,
    const float* __restrict__ l, const float* __restrict__ c2,
    float* __restrict__ out)
{
    GEMM_PROLOG
    const int fblk = blockIdx.x, qblk = blockIdx.y, b = blockIdx.z;
    const int ma = qblk * 128, nb = fblk * 128;
    const __half* Ah = P + (size_t)b * S1_ * S2_;
    const __half* Al = Ah;   // unused
    const __half* Bh = VT + (size_t)b * F_ * S2_;
    const __half* Bl = Bh;   // unused

    GEMM_MAIN(S2_, 1)

    const int bq0 = b * S1_ + qblk * 128;
    #pragma unroll
    for (int mi = 0; mi < 4; mi++) {
        int rl0 = wm * 64 + mi * 16 + (lane >> 2);
        float inv0 = 1.f / l[bq0 + rl0];
        float inv1 = 1.f / l[bq0 + rl0 + 8];
        size_t o0 = (size_t)(bq0 + rl0) * 256;
        size_t o1 = (size_t)(bq0 + rl0 + 8) * 256;
        #pragma unroll
        for (int nt = 0; nt < 4; nt++) {
            int col = fblk * 128 + wn * 32 + nt * 8 + 2 * lq;
            float c0 = c2[col], c1 = c2[col + 1];
            *(float2*)(out + o0 + col) =
                make_float2(acc[mi][nt][0] * inv0 + c0, acc[mi][nt][1] * inv0 + c1);
            *(float2*)(out + o1 + col) =
                make_float2(acc[mi][nt][2] * inv1 + c0, acc[mi][nt][3] * inv1 + c1);
        }
    }
}

// ---------------------------------------------------------------------------
extern "C" void kernel_launch(void* const* d_in, const int* in_sizes, int n_in,
                              void* d_out, int out_size)
{
    const float* feat1 = (const float*)d_in[0];
    const float* feat2 = (const float*)d_in[1];
    const float* Wq    = (const float*)d_in[2];
    const float* bq    = (const float*)d_in[3];
    const float* Wk    = (const float*)d_in[4];
    const float* bk    = (const float*)d_in[5];
    const float* Wv    = (const float*)d_in[6];
    const float* bv    = (const float*)d_in[7];
    const float* Wfc   = (const float*)d_in[8];
    const float* bfc   = (const float*)d_in[9];
    float* out = (float*)d_out;

    __half *f1h, *f1l, *f2h, *f2l, *Q, *K, *VT, *P;
    float *lp, *lv, *c2, *zv;
    __half (*wq)[D_ * F_]; __half (*wk)[D_ * F_]; __half (*w2)[D_ * F_];
    cudaGetSymbolAddress((void**)&f1h, g_f1h);
    cudaGetSymbolAddress((void**)&f1l, g_f1l);
    cudaGetSymbolAddress((void**)&f2h, g_f2h);
    cudaGetSymbolAddress((void**)&f2l, g_f2l);
    cudaGetSymbolAddress((void**)&wq,  g_wq);
    cudaGetSymbolAddress((void**)&wk,  g_wk);
    cudaGetSymbolAddress((void**)&w2,  g_w2);
    cudaGetSymbolAddress((void**)&c2,  g_c2);
    cudaGetSymbolAddress((void**)&zv,  g_zero);
    cudaGetSymbolAddress((void**)&Q,   g_Q);
    cudaGetSymbolAddress((void**)&K,   g_K);
    cudaGetSymbolAddress((void**)&VT,  g_VT);
    cudaGetSymbolAddress((void**)&P,   g_P);
    cudaGetSymbolAddress((void**)&lp,  g_lp);
    cudaGetSymbolAddress((void**)&lv,  g_l);

    split_f32_kernel<<<NFEAT / 4 / 256, 256>>>(feat1, f1h, f1l, NFEAT / 4);
    split_f32_kernel<<<NFEAT / 4 / 256, 256>>>(feat2, f2h, f2l, NFEAT / 4);
    split_weights_kernel<<<(2 * D_ * F_ + 255) / 256, 256>>>(Wq, Wk, wq[0], wq[1], wk[0], wk[1]);
    w2c2_kernel<<<257, 256>>>(Wv, Wfc, bv, bfc, w2[0], w2[1], c2);

    cudaFuncSetAttribute(gemm_qkv, cudaFuncAttributeMaxDynamicSharedMemorySize, GEMM_SMEM);
    cudaFuncSetAttribute(gemm_S,   cudaFuncAttributeMaxDynamicSharedMemorySize, GEMM_SMEM);
    cudaFuncSetAttribute(gemm_pv,  cudaFuncAttributeMaxDynamicSharedMemorySize, GEMM_SMEM);

    dim3 gq(2, B_ * S1_ / 128, 3);
    gemm_qkv<<<gq, 256, GEMM_SMEM>>>(f1h, f1l, f2h, f2l,
                                     wq[0], wq[1], wk[0], wk[1], w2[0], w2[1],
                                     bq, bk, zv, Q, K, VT);

    dim3 gs(S2_ / 128, S1_ / 128, B_);
    gemm_S<<<gs, 256, GEMM_SMEM>>>(Q, K, P, lp);

    lreduce_kernel<<<(B_ * S1_ + 255) / 256, 256>>>(lp, lv);

    dim3 gp(F_ / 128, S1_ / 128, B_);
    gemm_pv<<<gp, 256, GEMM_SMEM>>>(P, VT, lv, c2, out);
}

// round 15
// speedup vs baseline: 1.9250x; 1.1108x over previous
#include <cuda_runtime.h>
#include <cuda_fp16.h>
#include <cstdint>

#define B_  8
#define S1_ 2048
#define S2_ 2048
#define D_  512
#define F_  256
#define NQKV (B_ * S1_ * F_)
#define NFEAT (B_ * S1_ * D_)
#define NP   (B_ * S1_ * S2_)

__device__ __align__(16) __half g_f1h[NFEAT];
__device__ __align__(16) __half g_f1l[NFEAT];
__device__ __align__(16) __half g_f2h[NFEAT];
__device__ __align__(16) __half g_f2l[NFEAT];
__device__ __align__(16) __half g_wq[D_ * F_];      // plain fp16, transposed
__device__ __align__(16) __half g_wk[D_ * F_];
__device__ __align__(16) __half g_w2[D_ * F_];      // (Wv@Wfc)^T plain fp16
__device__ __align__(16) float  g_c2[F_];           // bv@Wfc + bfc
__device__ __align__(16) float  g_zero[F_];
__device__ __align__(16) __half g_Q  [NQKV];
__device__ __align__(16) __half g_K  [NQKV];
__device__ __align__(16) __half g_VT [NQKV];        // [b, f, t]
__device__ __align__(16) __half g_P  [NP];
__device__ __align__(16) float  g_lp [B_ * S1_ * 16];
__device__ __align__(16) float  g_l  [B_ * S1_];

__device__ __forceinline__ uint32_t smem_to_u32(const void* p) {
    uint32_t a;
    asm("{ .reg .u64 t; cvta.to.shared.u64 t, %1; cvt.u32.u64 %0, t; }" : "=r"(a) : "l"(p));
    return a;
}
__device__ __forceinline__ void ldsm4(uint32_t* r, uint32_t a) {
    asm volatile("ldmatrix.sync.aligned.m8n8.x4.shared.b16 {%0,%1,%2,%3}, [%4];"
        : "=r"(r[0]), "=r"(r[1]), "=r"(r[2]), "=r"(r[3]) : "r"(a));
}
__device__ __forceinline__ void mma_f16(float (&d)[4], const uint32_t* a, uint32_t b0, uint32_t b1) {
    asm volatile("mma.sync.aligned.m16n8k16.row.col.f32.f16.f16.f32 "
        "{%0,%1,%2,%3}, {%4,%5,%6,%7}, {%8,%9}, {%0,%1,%2,%3};"
        : "+f"(d[0]), "+f"(d[1]), "+f"(d[2]), "+f"(d[3])
        : "r"(a[0]), "r"(a[1]), "r"(a[2]), "r"(a[3]), "r"(b0), "r"(b1));
}
__device__ __forceinline__ void split_h(float x, __half& h, __half& l) {
    h = __float2half_rn(x);
    l = __float2half_rn(x - __half2float(h));
}
__device__ __forceinline__ uint32_t pack2(__half a, __half b) {
    return (uint32_t)__half_as_ushort(a) | ((uint32_t)__half_as_ushort(b) << 16);
}
#define CP_ASYNC16(dst, src) asm volatile("cp.async.cg.shared.global [%0], [%1], 16;" :: "r"(dst), "l"(src))
#define CP_COMMIT() asm volatile("cp.async.commit_group;" ::: "memory")
#define CP_WAIT0()  asm volatile("cp.async.wait_group 0;" ::: "memory")
#define CP_WAIT1()  asm volatile("cp.async.wait_group 1;" ::: "memory")

__global__ void __launch_bounds__(256) split_f32_kernel(
    const float* __restrict__ in, __half* __restrict__ h,
    __half* __restrict__ l, int n4)
{
    int i = blockIdx.x * 256 + threadIdx.x;
    if (i >= n4) return;
    float4 v = ((const float4*)in)[i];
    __half h0,l0,h1,l1,h2,l2,h3,l3;
    split_h(v.x,h0,l0); split_h(v.y,h1,l1);
    split_h(v.z,h2,l2); split_h(v.w,h3,l3);
    ((uint2*)h)[i] = make_uint2(pack2(h0,h1), pack2(h2,h3));
    ((uint2*)l)[i] = make_uint2(pack2(l0,l1), pack2(l2,l3));
}

// Wq, Wk: plain fp16 + transpose.
__global__ void __launch_bounds__(256) conv_weights_kernel(
    const float* __restrict__ Wq, const float* __restrict__ Wk,
    __half* __restrict__ wq, __half* __restrict__ wk)
{
    int i = blockIdx.x * 256 + threadIdx.x;
    const int NW = D_ * F_;
    if (i >= 2 * NW) return;
    int which = i / NW, j = i - which * NW;
    int n = j / D_, k = j - n * D_;
    (which == 0 ? wq : wk)[j] =
        __float2half_rn((which == 0 ? Wq : Wk)[(size_t)k * F_ + n]);
}

// W2 = Wv @ Wfc (fp32 -> plain fp16, transposed); c2 = bv@Wfc + bfc.
__global__ void __launch_bounds__(256) w2c2_kernel(
    const float* __restrict__ Wv, const float* __restrict__ Wfc,
    const float* __restrict__ bv, const float* __restrict__ bfc,
    __half* __restrict__ w2, float* __restrict__ c2)
{
    const int n = threadIdx.x;
    const int kb = blockIdx.x;
    if (kb == 256) {
        float s = bfc[n];
        #pragma unroll 8
        for (int j = 0; j < F_; j++) s += bv[j] * Wfc[(size_t)j * F_ + n];
        c2[n] = s;
        return;
    }
    __shared__ float wv[2][F_];
    wv[0][n] = Wv[(size_t)(kb * 2 + 0) * F_ + n];
    wv[1][n] = Wv[(size_t)(kb * 2 + 1) * F_ + n];
    __syncthreads();
    float s0 = 0.f, s1 = 0.f;
    #pragma unroll 8
    for (int j = 0; j < F_; j++) {
        float wf = Wfc[(size_t)j * F_ + n];
        s0 += wv[0][j] * wf;
        s1 += wv[1][j] * wf;
    }
    size_t i0 = (size_t)n * D_ + kb * 2;
    w2[i0]     = __float2half_rn(s0);
    w2[i0 + 1] = __float2half_rn(s1);
}

// ---------------------------------------------------------------------------
// Shared HMMA GEMM body: CTA 128x128, 8 warps (2m x 4n), warp 64x32,
// k-block 32, 3-stage cp.async (96KB), packed hi|lo 128B rows.
// NCH=1: A plain, B plain, 1 chain. NCH=2: A split, B plain, 2 chains.
// NCH=3: A split, B split, 3 chains.
// ---------------------------------------------------------------------------
#define GEMM_SMEM 98304

#define GEMM_PROLOG \
    extern __shared__ char sm[]; \
    const uint32_t smb = smem_to_u32(sm); \
    const int tid = threadIdx.x, lane = tid & 31, wid = tid >> 5; \
    const int wm = wid & 1, wn = wid >> 1; \
    const int arow = wm * 64 + (lane & 15); \
    const int as = arow & 7, ah = lane >> 4; \
    const int brow = wn * 32 + ((lane >> 4) << 3) + (lane & 7); \
    const int bs = lane & 7, bh2 = (lane >> 3) & 1; \
    const int lq = lane & 3;

#define GISSUE(buf, k0, KDV, NCH) do { \
    uint32_t gb = smb + (buf) * 32768; \
    _Pragma("unroll") \
    for (int p = 0; p < 4; p++) { \
        int id = p * 256 + tid; int r = id >> 3, c = id & 7; \
        uint32_t d = r * 128 + (((uint32_t)(c ^ (r & 7))) << 4); \
        if ((NCH) >= 2 || c < 4) { \
            const __half* sa = (c < 4) ? Ah + (size_t)(ma + r) * (KDV) + (k0) + c * 8 \
                                       : Al + (size_t)(ma + r) * (KDV) + (k0) + (c - 4) * 8; \
            CP_ASYNC16(gb + d, sa); \
        } \
        if ((NCH) == 3 || c < 4) { \
            const __half* sb = (c < 4) ? Bh + (size_t)(nb + r) * (KDV) + (k0) + c * 8 \
                                       : Bl + (size_t)(nb + r) * (KDV) + (k0) + (c - 4) * 8; \
            CP_ASYNC16(gb + 16384 + d, sb); \
        } \
    } } while (0)

#define GEMM_MAIN(KDV, NCH) \
    float acc[4][4][4]; \
    _Pragma("unroll") \
    for (int i = 0; i < 4; i++) \
        _Pragma("unroll") \
        for (int j = 0; j < 4; j++) \
            _Pragma("unroll") \
            for (int k = 0; k < 4; k++) acc[i][j][k] = 0.f; \
    { \
        const int T = (KDV) / 32; \
        GISSUE(0, 0, KDV, NCH); CP_COMMIT(); \
        if (T > 1) { GISSUE(1, 32, KDV, NCH); CP_COMMIT(); } \
        for (int t = 0; t < T; t++) { \
            if (t + 1 < T) { CP_WAIT1(); } else { CP_WAIT0(); } \
            __syncthreads(); \
            if (t + 2 < T) { GISSUE((t + 2) % 3, (t + 2) * 32, KDV, NCH); CP_COMMIT(); } \
            const int cur = t % 3; \
            uint32_t aP = smb + cur * 32768 + arow * 128; \
            uint32_t bP = smb + cur * 32768 + 16384 + brow * 128; \
            _Pragma("unroll") \
            for (int ks = 0; ks < 2; ks++) { \
                uint32_t hcA = (uint32_t)(2 * ks + ah); \
                uint32_t aq[4][4], alr[4][4]; \
                _Pragma("unroll") \
                for (int mi = 0; mi < 4; mi++) { \
                    ldsm4(aq[mi], aP + mi * 2048 + ((hcA ^ (uint32_t)as) << 4)); \
                    if ((NCH) >= 2) \
                        ldsm4(alr[mi], aP + mi * 2048 + (((hcA + 4) ^ (uint32_t)as) << 4)); \
                } \
                uint32_t hcB = (uint32_t)(2 * ks + bh2); \
                _Pragma("unroll") \
                for (int ni = 0; ni < 2; ni++) { \
                    uint32_t bhh[4], bll[4]; \
                    ldsm4(bhh, bP + ni * 2048 + ((hcB ^ (uint32_t)bs) << 4)); \
                    if ((NCH) == 3) \
                        ldsm4(bll, bP + ni * 2048 + (((hcB + 4) ^ (uint32_t)bs) << 4)); \
                    _Pragma("unroll") \
                    for (int mi = 0; mi < 4; mi++) { \
                        mma_f16(acc[mi][2*ni],   aq[mi], bhh[0], bhh[1]); \
                        mma_f16(acc[mi][2*ni+1], aq[mi], bhh[2], bhh[3]); \
                        if ((NCH) >= 2) { \
                            mma_f16(acc[mi][2*ni],   alr[mi], bhh[0], bhh[1]); \
                            mma_f16(acc[mi][2*ni+1], alr[mi], bhh[2], bhh[3]); \
                        } \
                        if ((NCH) == 3) { \
                            mma_f16(acc[mi][2*ni],   aq[mi], bll[0], bll[1]); \
                            mma_f16(acc[mi][2*ni+1], aq[mi], bll[2], bll[3]); \
                        } \
                    } \
                } \
            } \
        } \
        __syncthreads(); \
    }

// ---------------------------------------------------------------------------
// Fused Q/K/V' projections: 2-chain (feat split x plain fp16 weight).
// z=0 Q, z=1 K (row-major), z=2 V'T (transposed [b,f,t]).
// ---------------------------------------------------------------------------
__global__ void __launch_bounds__(256, 2) gemm_qkv(
    const __half* __restrict__ f1h, const __half* __restrict__ f1l,
    const __half* __restrict__ f2h, const __half* __restrict__ f2l,
    const __half* __restrict__ wq, const __half* __restrict__ wk,
    const __half* __restrict__ w2,
    const float* __restrict__ bq, const float* __restrict__ bk, const float* __restrict__ bz,
    __half* __restrict__ Q, __half* __restrict__ K, __half* __restrict__ VT)
{
    GEMM_PROLOG
    const int n0 = blockIdx.x * 128, m0 = blockIdx.y * 128;
    const int z = blockIdx.z;
    const int ma = m0, nb = n0;
    const __half* Ah = z == 0 ? f1h : f2h;
    const __half* Al = z == 0 ? f1l : f2l;
    const __half* Bh = z == 0 ? wq : (z == 1 ? wk : w2);
    const __half* Bl = Bh;   // unused (NCH=2)
    const float* bias = z == 0 ? bq : (z == 1 ? bk : bz);
    __half* O = z == 0 ? Q : (z == 1 ? K : VT);

    GEMM_MAIN(D_, 2)

    #pragma unroll
    for (int mi = 0; mi < 4; mi++) {
        int r0 = m0 + wm * 64 + mi * 16 + (lane >> 2);
        int r1 = r0 + 8;
        #pragma unroll
        for (int nt = 0; nt < 4; nt++) {
            int col = n0 + wn * 32 + nt * 8 + 2 * lq;
            float b0 = bias[col], b1 = bias[col + 1];
            __half h0 = __float2half_rn(acc[mi][nt][0] + b0);
            __half h1 = __float2half_rn(acc[mi][nt][1] + b1);
            __half h2 = __float2half_rn(acc[mi][nt][2] + b0);
            __half h3 = __float2half_rn(acc[mi][nt][3] + b1);
            if (z < 2) {
                *(uint32_t*)(O + (size_t)r0 * 256 + col) = pack2(h0, h1);
                *(uint32_t*)(O + (size_t)r1 * 256 + col) = pack2(h2, h3);
            } else {
                size_t o0 = (size_t)(r0 >> 11) * (F_ * S2_) + (size_t)col * S2_ + (r0 & 2047);
                size_t o1 = (size_t)(r1 >> 11) * (F_ * S2_) + (size_t)col * S2_ + (r1 & 2047);
                O[o0] = h0; O[o0 + S2_] = h1;
                O[o1] = h2; O[o1 + S2_] = h3;
            }
        }
    }
}

// ---------------------------------------------------------------------------
// S-kernel: P = exp(scale * Q@K^T) fp16 + per-128-block row sums. 1 chain.
// ---------------------------------------------------------------------------
__global__ void __launch_bounds__(256, 2) gemm_S(
    const __half* __restrict__ Q, const __half* __restrict__ K,
    __half* __restrict__ P, float* __restrict__ lp)
{
    GEMM_PROLOG
    const int kblk = blockIdx.x, qblk = blockIdx.y, b = blockIdx.z;
    const int ma = qblk * 128, nb = kblk * 128;
    const __half* Ah = Q + (size_t)b * S1_ * F_;
    const __half* Al = Ah;   // unused
    const __half* Bh = K + (size_t)b * S2_ * F_;
    const __half* Bl = Bh;   // unused

    GEMM_MAIN(F_, 1)

    const float scale = 0.0625f;
    const int bq0 = b * S1_ + qblk * 128;
    const int kb0 = kblk * 128;
    float rsum[4][2];
    #pragma unroll
    for (int mi = 0; mi < 4; mi++) { rsum[mi][0] = 0.f; rsum[mi][1] = 0.f; }

    #pragma unroll
    for (int mi = 0; mi < 4; mi++) {
        int rl0 = wm * 64 + mi * 16 + (lane >> 2);
        size_t pb0 = (size_t)(bq0 + rl0) * S2_ + kb0;
        size_t pb1 = (size_t)(bq0 + rl0 + 8) * S2_ + kb0;
        #pragma unroll
        for (int nt = 0; nt < 4; nt++) {
            int col = wn * 32 + nt * 8 + 2 * lq;
            float p0 = __expf(acc[mi][nt][0] * scale);
            float p1 = __expf(acc[mi][nt][1] * scale);
            float p2 = __expf(acc[mi][nt][2] * scale);
            float p3 = __expf(acc[mi][nt][3] * scale);
            rsum[mi][0] += p0 + p1;
            rsum[mi][1] += p2 + p3;
            *(uint32_t*)(P + pb0 + col) = pack2(__float2half_rn(p0), __float2half_rn(p1));
            *(uint32_t*)(P + pb1 + col) = pack2(__float2half_rn(p2), __float2half_rn(p3));
        }
    }
    #pragma unroll
    for (int mi = 0; mi < 4; mi++) {
        #pragma unroll
        for (int u = 0; u < 2; u++) {
            rsum[mi][u] += __shfl_xor_sync(0xffffffffu, rsum[mi][u], 1);
            rsum[mi][u] += __shfl_xor_sync(0xffffffffu, rsum[mi][u], 2);
        }
    }
    float* red = (float*)sm;
    __syncthreads();
    if (lq == 0) {
        #pragma unroll
        for (int mi = 0; mi < 4; mi++) {
            int rl = wm * 64 + mi * 16 + (lane >> 2);
            red[wn * 128 + rl]     = rsum[mi][0];
            red[wn * 128 + rl + 8] = rsum[mi][1];
        }
    }
    __syncthreads();
    if (tid < 128)
        lp[(size_t)(bq0 + tid) * 16 + kblk] =
            (red[tid] + red[128 + tid]) + (red[256 + tid] + red[384 + tid]);
}

__global__ void __launch_bounds__(256) lreduce_kernel(const float* __restrict__ lp,
                                                      float* __restrict__ l)
{
    int i = blockIdx.x * 256 + threadIdx.x;
    if (i >= B_ * S1_) return;
    float s = 0.f;
    #pragma unroll
    for (int j = 0; j < 16; j++) s += lp[(size_t)i * 16 + j];
    l[i] = s;
}

// ---------------------------------------------------------------------------
// PV-kernel: out = (P@VT^T)/l + c2 (final fp32 output). 1 chain.
// ---------------------------------------------------------------------------
__global__ void __launch_bounds__(256, 2) gemm_pv(
    const __half* __restrict__ P, const __half* __restrict__ VT,
    const float* __restrict__ l, const float* __restrict__ c2,
    float* __restrict__ out)
{
    GEMM_PROLOG
    const int fblk = blockIdx.x, qblk = blockIdx.y, b = blockIdx.z;
    const int ma = qblk * 128, nb = fblk * 128;
    const __half* Ah = P + (size_t)b * S1_ * S2_;
    const __half* Al = Ah;   // unused
    const __half* Bh = VT + (size_t)b * F_ * S2_;
    const __half* Bl = Bh;   // unused

    GEMM_MAIN(S2_, 1)

    const int bq0 = b * S1_ + qblk * 128;
    #pragma unroll
    for (int mi = 0; mi < 4; mi++) {
        int rl0 = wm * 64 + mi * 16 + (lane >> 2);
        float inv0 = 1.f / l[bq0 + rl0];
        float inv1 = 1.f / l[bq0 + rl0 + 8];
        size_t o0 = (size_t)(bq0 + rl0) * 256;
        size_t o1 = (size_t)(bq0 + rl0 + 8) * 256;
        #pragma unroll
        for (int nt = 0; nt < 4; nt++) {
            int col = fblk * 128 + wn * 32 + nt * 8 + 2 * lq;
            float c0 = c2[col], c1 = c2[col + 1];
            *(float2*)(out + o0 + col) =
                make_float2(acc[mi][nt][0] * inv0 + c0, acc[mi][nt][1] * inv0 + c1);
            *(float2*)(out + o1 + col) =
                make_float2(acc[mi][nt][2] * inv1 + c0, acc[mi][nt][3] * inv1 + c1);
        }
    }
}

// ---------------------------------------------------------------------------
extern "C" void kernel_launch(void* const* d_in, const int* in_sizes, int n_in,
                              void* d_out, int out_size)
{
    const float* feat1 = (const float*)d_in[0];
    const float* feat2 = (const float*)d_in[1];
    const float* Wq    = (const float*)d_in[2];
    const float* bq    = (const float*)d_in[3];
    const float* Wk    = (const float*)d_in[4];
    const float* bk    = (const float*)d_in[5];
    const float* Wv    = (const float*)d_in[6];
    const float* bv    = (const float*)d_in[7];
    const float* Wfc   = (const float*)d_in[8];
    const float* bfc   = (const float*)d_in[9];
    float* out = (float*)d_out;

    __half *f1h, *f1l, *f2h, *f2l, *Q, *K, *VT, *P, *wq, *wk, *w2;
    float *lp, *lv, *c2, *zv;
    cudaGetSymbolAddress((void**)&f1h, g_f1h);
    cudaGetSymbolAddress((void**)&f1l, g_f1l);
    cudaGetSymbolAddress((void**)&f2h, g_f2h);
    cudaGetSymbolAddress((void**)&f2l, g_f2l);
    cudaGetSymbolAddress((void**)&wq,  g_wq);
    cudaGetSymbolAddress((void**)&wk,  g_wk);
    cudaGetSymbolAddress((void**)&w2,  g_w2);
    cudaGetSymbolAddress((void**)&c2,  g_c2);
    cudaGetSymbolAddress((void**)&zv,  g_zero);
    cudaGetSymbolAddress((void**)&Q,   g_Q);
    cudaGetSymbolAddress((void**)&K,   g_K);
    cudaGetSymbolAddress((void**)&VT,  g_VT);
    cudaGetSymbolAddress((void**)&P,   g_P);
    cudaGetSymbolAddress((void**)&lp,  g_lp);
    cudaGetSymbolAddress((void**)&lv,  g_l);

    split_f32_kernel<<<NFEAT / 4 / 256, 256>>>(feat1, f1h, f1l, NFEAT / 4);
    split_f32_kernel<<<NFEAT / 4 / 256, 256>>>(feat2, f2h, f2l, NFEAT / 4);
    conv_weights_kernel<<<(2 * D_ * F_ + 255) / 256, 256>>>(Wq, Wk, wq, wk);
    w2c2_kernel<<<257, 256>>>(Wv, Wfc, bv, bfc, w2, c2);

    cudaFuncSetAttribute(gemm_qkv, cudaFuncAttributeMaxDynamicSharedMemorySize, GEMM_SMEM);
    cudaFuncSetAttribute(gemm_S,   cudaFuncAttributeMaxDynamicSharedMemorySize, GEMM_SMEM);
    cudaFuncSetAttribute(gemm_pv,  cudaFuncAttributeMaxDynamicSharedMemorySize, GEMM_SMEM);

    dim3 gq(2, B_ * S1_ / 128, 3);
    gemm_qkv<<<gq, 256, GEMM_SMEM>>>(f1h, f1l, f2h, f2l, wq, wk, w2,
                                     bq, bk, zv, Q, K, VT);

    dim3 gs(S2_ / 128, S1_ / 128, B_);
    gemm_S<<<gs, 256, GEMM_SMEM>>>(Q, K, P, lp);

    lreduce_kernel<<<(B_ * S1_ + 255) / 256, 256>>>(lp, lv);

    dim3 gp(F_ / 128, S1_ / 128, B_);
    gemm_pv<<<gp, 256, GEMM_SMEM>>>(P, VT, lv, c2, out);
}

// round 16
// speedup vs baseline: 2.0841x; 1.0827x over previous
#include <cuda_runtime.h>
#include <cuda_fp16.h>
#include <cstdint>

#define B_  8
#define S1_ 2048
#define S2_ 2048
#define D_  512
#define F_  256
#define NQKV (B_ * S1_ * F_)
#define NFEAT (B_ * S1_ * D_)
#define NP   (B_ * S1_ * S2_)

__device__ __align__(16) __half g_f1 [NFEAT];       // plain fp16
__device__ __align__(16) __half g_f2 [NFEAT];
__device__ __align__(16) __half g_wq[D_ * F_];      // plain fp16, transposed
__device__ __align__(16) __half g_wk[D_ * F_];
__device__ __align__(16) __half g_w2[D_ * F_];      // (Wv@Wfc)^T plain fp16
__device__ __align__(16) float  g_c2[F_];           // bv@Wfc + bfc
__device__ __align__(16) float  g_zero[F_];
__device__ __align__(16) __half g_Q  [NQKV];
__device__ __align__(16) __half g_K  [NQKV];
__device__ __align__(16) __half g_VT [NQKV];        // [b, f, t]
__device__ __align__(16) __half g_P  [NP];
__device__ __align__(16) float  g_lp [B_ * S1_ * 16];
__device__ __align__(16) float  g_l  [B_ * S1_];

__device__ __forceinline__ uint32_t smem_to_u32(const void* p) {
    uint32_t a;
    asm("{ .reg .u64 t; cvta.to.shared.u64 t, %1; cvt.u32.u64 %0, t; }" : "=r"(a) : "l"(p));
    return a;
}
__device__ __forceinline__ void ldsm4(uint32_t* r, uint32_t a) {
    asm volatile("ldmatrix.sync.aligned.m8n8.x4.shared.b16 {%0,%1,%2,%3}, [%4];"
        : "=r"(r[0]), "=r"(r[1]), "=r"(r[2]), "=r"(r[3]) : "r"(a));
}
__device__ __forceinline__ void mma_f16(float (&d)[4], const uint32_t* a, uint32_t b0, uint32_t b1) {
    asm volatile("mma.sync.aligned.m16n8k16.row.col.f32.f16.f16.f32 "
        "{%0,%1,%2,%3}, {%4,%5,%6,%7}, {%8,%9}, {%0,%1,%2,%3};"
        : "+f"(d[0]), "+f"(d[1]), "+f"(d[2]), "+f"(d[3])
        : "r"(a[0]), "r"(a[1]), "r"(a[2]), "r"(a[3]), "r"(b0), "r"(b1));
}
__device__ __forceinline__ uint32_t pack2(__half a, __half b) {
    return (uint32_t)__half_as_ushort(a) | ((uint32_t)__half_as_ushort(b) << 16);
}
#define CP_ASYNC16(dst, src) asm volatile("cp.async.cg.shared.global [%0], [%1], 16;" :: "r"(dst), "l"(src))
#define CP_COMMIT() asm volatile("cp.async.commit_group;" ::: "memory")
#define CP_WAIT0()  asm volatile("cp.async.wait_group 0;" ::: "memory")
#define CP_WAIT1()  asm volatile("cp.async.wait_group 1;" ::: "memory")

// fp32 -> plain fp16 convert (vectorized)
__global__ void __launch_bounds__(256) conv_f32_kernel(
    const float* __restrict__ in, __half* __restrict__ o, int n4)
{
    int i = blockIdx.x * 256 + threadIdx.x;
    if (i >= n4) return;
    float4 v = ((const float4*)in)[i];
    ((uint2*)o)[i] = make_uint2(
        pack2(__float2half_rn(v.x), __float2half_rn(v.y)),
        pack2(__float2half_rn(v.z), __float2half_rn(v.w)));
}

// Wq, Wk: plain fp16 + transpose.
__global__ void __launch_bounds__(256) conv_weights_kernel(
    const float* __restrict__ Wq, const float* __restrict__ Wk,
    __half* __restrict__ wq, __half* __restrict__ wk)
{
    int i = blockIdx.x * 256 + threadIdx.x;
    const int NW = D_ * F_;
    if (i >= 2 * NW) return;
    int which = i / NW, j = i - which * NW;
    int n = j / D_, k = j - n * D_;
    (which == 0 ? wq : wk)[j] =
        __float2half_rn((which == 0 ? Wq : Wk)[(size_t)k * F_ + n]);
}

// W2 = Wv @ Wfc (fp32 -> plain fp16, transposed); c2 = bv@Wfc + bfc.
// 8 independent accumulators -> MLP 8 on the L2-latency-bound j-loop.
__global__ void __launch_bounds__(256) w2c2_kernel(
    const float* __restrict__ Wv, const float* __restrict__ Wfc,
    const float* __restrict__ bv, const float* __restrict__ bfc,
    __half* __restrict__ w2, float* __restrict__ c2)
{
    const int n = threadIdx.x;
    const int kb = blockIdx.x;
    if (kb == 256) {
        float part[8] = {0,0,0,0,0,0,0,0};
        for (int jb = 0; jb < F_; jb += 8)
            #pragma unroll
            for (int u = 0; u < 8; u++)
                part[u] += bv[jb + u] * Wfc[(size_t)(jb + u) * F_ + n];
        c2[n] = bfc[n] + ((part[0]+part[1])+(part[2]+part[3]))
                       + ((part[4]+part[5])+(part[6]+part[7]));
        return;
    }
    __shared__ float wv[2][F_];
    wv[0][n] = Wv[(size_t)(kb * 2 + 0) * F_ + n];
    wv[1][n] = Wv[(size_t)(kb * 2 + 1) * F_ + n];
    __syncthreads();
    float p0[8] = {0,0,0,0,0,0,0,0}, p1[8] = {0,0,0,0,0,0,0,0};
    for (int jb = 0; jb < F_; jb += 8) {
        #pragma unroll
        for (int u = 0; u < 8; u++) {
            float wf = Wfc[(size_t)(jb + u) * F_ + n];
            p0[u] += wv[0][jb + u] * wf;
            p1[u] += wv[1][jb + u] * wf;
        }
    }
    float s0 = ((p0[0]+p0[1])+(p0[2]+p0[3])) + ((p0[4]+p0[5])+(p0[6]+p0[7]));
    float s1 = ((p1[0]+p1[1])+(p1[2]+p1[3])) + ((p1[4]+p1[5])+(p1[6]+p1[7]));
    size_t i0 = (size_t)n * D_ + kb * 2;
    w2[i0]     = __float2half_rn(s0);
    w2[i0 + 1] = __float2half_rn(s1);
}

// ---------------------------------------------------------------------------
// Shared HMMA GEMM body: CTA 128x128, 8 warps (2m x 4n), warp 64x32,
// k-block 32, 3-stage cp.async (96KB), single-chain pure fp16.
// Tiles use hi chunks (c<4) of the 128B row only.
// ---------------------------------------------------------------------------
#define GEMM_SMEM 98304

#define GEMM_PROLOG \
    extern __shared__ char sm[]; \
    const uint32_t smb = smem_to_u32(sm); \
    const int tid = threadIdx.x, lane = tid & 31, wid = tid >> 5; \
    const int wm = wid & 1, wn = wid >> 1; \
    const int arow = wm * 64 + (lane & 15); \
    const int as = arow & 7, ah = lane >> 4; \
    const int brow = wn * 32 + ((lane >> 4) << 3) + (lane & 7); \
    const int bs = lane & 7, bh2 = (lane >> 3) & 1; \
    const int lq = lane & 3;

#define GISSUE(buf, k0, KDV) do { \
    uint32_t gb = smb + (buf) * 32768; \
    _Pragma("unroll") \
    for (int p = 0; p < 4; p++) { \
        int id = p * 256 + tid; int r = id >> 3, c = id & 7; \
        if (c < 4) { \
            uint32_t d = r * 128 + (((uint32_t)(c ^ (r & 7))) << 4); \
            CP_ASYNC16(gb + d,         Ag + (size_t)(ma + r) * (KDV) + (k0) + c * 8); \
            CP_ASYNC16(gb + 16384 + d, Bg + (size_t)(nb + r) * (KDV) + (k0) + c * 8); \
        } \
    } } while (0)

#define GEMM_MAIN(KDV) \
    float acc[4][4][4]; \
    _Pragma("unroll") \
    for (int i = 0; i < 4; i++) \
        _Pragma("unroll") \
        for (int j = 0; j < 4; j++) \
            _Pragma("unroll") \
            for (int k = 0; k < 4; k++) acc[i][j][k] = 0.f; \
    { \
        const int T = (KDV) / 32; \
        GISSUE(0, 0, KDV); CP_COMMIT(); \
        if (T > 1) { GISSUE(1, 32, KDV); CP_COMMIT(); } \
        for (int t = 0; t < T; t++) { \
            if (t + 1 < T) { CP_WAIT1(); } else { CP_WAIT0(); } \
            __syncthreads(); \
            if (t + 2 < T) { GISSUE((t + 2) % 3, (t + 2) * 32, KDV); CP_COMMIT(); } \
            const int cur = t % 3; \
            uint32_t aP = smb + cur * 32768 + arow * 128; \
            uint32_t bP = smb + cur * 32768 + 16384 + brow * 128; \
            _Pragma("unroll") \
            for (int ks = 0; ks < 2; ks++) { \
                uint32_t hcA = (uint32_t)(2 * ks + ah); \
                uint32_t aq[4][4]; \
                _Pragma("unroll") \
                for (int mi = 0; mi < 4; mi++) \
                    ldsm4(aq[mi], aP + mi * 2048 + ((hcA ^ (uint32_t)as) << 4)); \
                uint32_t hcB = (uint32_t)(2 * ks + bh2); \
                _Pragma("unroll") \
                for (int ni = 0; ni < 2; ni++) { \
                    uint32_t bhh[4]; \
                    ldsm4(bhh, bP + ni * 2048 + ((hcB ^ (uint32_t)bs) << 4)); \
                    _Pragma("unroll") \
                    for (int mi = 0; mi < 4; mi++) { \
                        mma_f16(acc[mi][2*ni],   aq[mi], bhh[0], bhh[1]); \
                        mma_f16(acc[mi][2*ni+1], aq[mi], bhh[2], bhh[3]); \
                    } \
                } \
            } \
        } \
        __syncthreads(); \
    }

// ---------------------------------------------------------------------------
// Fused Q/K/V' projections: single chain, plain fp16 in/out.
// z=0 Q, z=1 K (row-major), z=2 V'T (transposed [b,f,t]).
// ---------------------------------------------------------------------------
__global__ void __launch_bounds__(256, 2) gemm_qkv(
    const __half* __restrict__ f1, const __half* __restrict__ f2,
    const __half* __restrict__ wq, const __half* __restrict__ wk,
    const __half* __restrict__ w2,
    const float* __restrict__ bq, const float* __restrict__ bk, const float* __restrict__ bz,
    __half* __restrict__ Q, __half* __restrict__ K, __half* __restrict__ VT)
{
    GEMM_PROLOG
    const int n0 = blockIdx.x * 128, m0 = blockIdx.y * 128;
    const int z = blockIdx.z;
    const int ma = m0, nb = n0;
    const __half* Ag = z == 0 ? f1 : f2;
    const __half* Bg = z == 0 ? wq : (z == 1 ? wk : w2);
    const float* bias = z == 0 ? bq : (z == 1 ? bk : bz);
    __half* O = z == 0 ? Q : (z == 1 ? K : VT);

    GEMM_MAIN(D_)

    #pragma unroll
    for (int mi = 0; mi < 4; mi++) {
        int r0 = m0 + wm * 64 + mi * 16 + (lane >> 2);
        int r1 = r0 + 8;
        #pragma unroll
        for (int nt = 0; nt < 4; nt++) {
            int col = n0 + wn * 32 + nt * 8 + 2 * lq;
            float b0 = bias[col], b1 = bias[col + 1];
            __half h0 = __float2half_rn(acc[mi][nt][0] + b0);
            __half h1 = __float2half_rn(acc[mi][nt][1] + b1);
            __half h2 = __float2half_rn(acc[mi][nt][2] + b0);
            __half h3 = __float2half_rn(acc[mi][nt][3] + b1);
            if (z < 2) {
                *(uint32_t*)(O + (size_t)r0 * 256 + col) = pack2(h0, h1);
                *(uint32_t*)(O + (size_t)r1 * 256 + col) = pack2(h2, h3);
            } else {
                size_t o0 = (size_t)(r0 >> 11) * (F_ * S2_) + (size_t)col * S2_ + (r0 & 2047);
                size_t o1 = (size_t)(r1 >> 11) * (F_ * S2_) + (size_t)col * S2_ + (r1 & 2047);
                O[o0] = h0; O[o0 + S2_] = h1;
                O[o1] = h2; O[o1 + S2_] = h3;
            }
        }
    }
}

// ---------------------------------------------------------------------------
// S-kernel: P = exp(scale * Q@K^T) fp16 + per-128-block row sums.
// ---------------------------------------------------------------------------
__global__ void __launch_bounds__(256, 2) gemm_S(
    const __half* __restrict__ Q, const __half* __restrict__ K,
    __half* __restrict__ P, float* __restrict__ lp)
{
    GEMM_PROLOG
    const int kblk = blockIdx.x, qblk = blockIdx.y, b = blockIdx.z;
    const int ma = qblk * 128, nb = kblk * 128;
    const __half* Ag = Q + (size_t)b * S1_ * F_;
    const __half* Bg = K + (size_t)b * S2_ * F_;

    GEMM_MAIN(F_)

    const float scale = 0.0625f;
    const int bq0 = b * S1_ + qblk * 128;
    const int kb0 = kblk * 128;
    float rsum[4][2];
    #pragma unroll
    for (int mi = 0; mi < 4; mi++) { rsum[mi][0] = 0.f; rsum[mi][1] = 0.f; }

    #pragma unroll
    for (int mi = 0; mi < 4; mi++) {
        int rl0 = wm * 64 + mi * 16 + (lane >> 2);
        size_t pb0 = (size_t)(bq0 + rl0) * S2_ + kb0;
        size_t pb1 = (size_t)(bq0 + rl0 + 8) * S2_ + kb0;
        #pragma unroll
        for (int nt = 0; nt < 4; nt++) {
            int col = wn * 32 + nt * 8 + 2 * lq;
            float p0 = __expf(acc[mi][nt][0] * scale);
            float p1 = __expf(acc[mi][nt][1] * scale);
            float p2 = __expf(acc[mi][nt][2] * scale);
            float p3 = __expf(acc[mi][nt][3] * scale);
            rsum[mi][0] += p0 + p1;
            rsum[mi][1] += p2 + p3;
            *(uint32_t*)(P + pb0 + col) = pack2(__float2half_rn(p0), __float2half_rn(p1));
            *(uint32_t*)(P + pb1 + col) = pack2(__float2half_rn(p2), __float2half_rn(p3));
        }
    }
    #pragma unroll
    for (int mi = 0; mi < 4; mi++) {
        #pragma unroll
        for (int u = 0; u < 2; u++) {
            rsum[mi][u] += __shfl_xor_sync(0xffffffffu, rsum[mi][u], 1);
            rsum[mi][u] += __shfl_xor_sync(0xffffffffu, rsum[mi][u], 2);
        }
    }
    float* red = (float*)sm;
    __syncthreads();
    if (lq == 0) {
        #pragma unroll
        for (int mi = 0; mi < 4; mi++) {
            int rl = wm * 64 + mi * 16 + (lane >> 2);
            red[wn * 128 + rl]     = rsum[mi][0];
            red[wn * 128 + rl + 8] = rsum[mi][1];
        }
    }
    __syncthreads();
    if (tid < 128)
        lp[(size_t)(bq0 + tid) * 16 + kblk] =
            (red[tid] + red[128 + tid]) + (red[256 + tid] + red[384 + tid]);
}

__global__ void __launch_bounds__(256) lreduce_kernel(const float* __restrict__ lp,
                                                      float* __restrict__ l)
{
    int i = blockIdx.x * 256 + threadIdx.x;
    if (i >= B_ * S1_) return;
    float s = 0.f;
    #pragma unroll
    for (int j = 0; j < 16; j++) s += lp[(size_t)i * 16 + j];
    l[i] = s;
}

// ---------------------------------------------------------------------------
// PV-kernel: out = (P@VT^T)/l + c2 (final fp32 output).
// ---------------------------------------------------------------------------
__global__ void __launch_bounds__(256, 2) gemm_pv(
    const __half* __restrict__ P, const __half* __restrict__ VT,
    const float* __restrict__ l, const float* __restrict__ c2,
    float* __restrict__ out)
{
    GEMM_PROLOG
    const int fblk = blockIdx.x, qblk = blockIdx.y, b = blockIdx.z;
    const int ma = qblk * 128, nb = fblk * 128;
    const __half* Ag = P + (size_t)b * S1_ * S2_;
    const __half* Bg = VT + (size_t)b * F_ * S2_;

    GEMM_MAIN(S2_)

    const int bq0 = b * S1_ + qblk * 128;
    #pragma unroll
    for (int mi = 0; mi < 4; mi++) {
        int rl0 = wm * 64 + mi * 16 + (lane >> 2);
        float inv0 = 1.f / l[bq0 + rl0];
        float inv1 = 1.f / l[bq0 + rl0 + 8];
        size_t o0 = (size_t)(bq0 + rl0) * 256;
        size_t o1 = (size_t)(bq0 + rl0 + 8) * 256;
        #pragma unroll
        for (int nt = 0; nt < 4; nt++) {
            int col = fblk * 128 + wn * 32 + nt * 8 + 2 * lq;
            float c0 = c2[col], c1 = c2[col + 1];
            *(float2*)(out + o0 + col) =
                make_float2(acc[mi][nt][0] * inv0 + c0, acc[mi][nt][1] * inv0 + c1);
            *(float2*)(out + o1 + col) =
                make_float2(acc[mi][nt][2] * inv1 + c0, acc[mi][nt][3] * inv1 + c1);
        }
    }
}

// ---------------------------------------------------------------------------
extern "C" void kernel_launch(void* const* d_in, const int* in_sizes, int n_in,
                              void* d_out, int out_size)
{
    const float* feat1 = (const float*)d_in[0];
    const float* feat2 = (const float*)d_in[1];
    const float* Wq    = (const float*)d_in[2];
    const float* bq    = (const float*)d_in[3];
    const float* Wk    = (const float*)d_in[4];
    const float* bk    = (const float*)d_in[5];
    const float* Wv    = (const float*)d_in[6];
    const float* bv    = (const float*)d_in[7];
    const float* Wfc   = (const float*)d_in[8];
    const float* bfc   = (const float*)d_in[9];
    float* out = (float*)d_out;

    __half *f1, *f2, *Q, *K, *VT, *P, *wq, *wk, *w2;
    float *lp, *lv, *c2, *zv;
    cudaGetSymbolAddress((void**)&f1,  g_f1);
    cudaGetSymbolAddress((void**)&f2,  g_f2);
    cudaGetSymbolAddress((void**)&wq,  g_wq);
    cudaGetSymbolAddress((void**)&wk,  g_wk);
    cudaGetSymbolAddress((void**)&w2,  g_w2);
    cudaGetSymbolAddress((void**)&c2,  g_c2);
    cudaGetSymbolAddress((void**)&zv,  g_zero);
    cudaGetSymbolAddress((void**)&Q,   g_Q);
    cudaGetSymbolAddress((void**)&K,   g_K);
    cudaGetSymbolAddress((void**)&VT,  g_VT);
    cudaGetSymbolAddress((void**)&P,   g_P);
    cudaGetSymbolAddress((void**)&lp,  g_lp);
    cudaGetSymbolAddress((void**)&lv,  g_l);

    conv_f32_kernel<<<NFEAT / 4 / 256, 256>>>(feat1, f1, NFEAT / 4);
    conv_f32_kernel<<<NFEAT / 4 / 256, 256>>>(feat2, f2, NFEAT / 4);
    conv_weights_kernel<<<(2 * D_ * F_ + 255) / 256, 256>>>(Wq, Wk, wq, wk);
    w2c2_kernel<<<257, 256>>>(Wv, Wfc, bv, bfc, w2, c2);

    cudaFuncSetAttribute(gemm_qkv, cudaFuncAttributeMaxDynamicSharedMemorySize, GEMM_SMEM);
    cudaFuncSetAttribute(gemm_S,   cudaFuncAttributeMaxDynamicSharedMemorySize, GEMM_SMEM);
    cudaFuncSetAttribute(gemm_pv,  cudaFuncAttributeMaxDynamicSharedMemorySize, GEMM_SMEM);

    dim3 gq(2, B_ * S1_ / 128, 3);
    gemm_qkv<<<gq, 256, GEMM_SMEM>>>(f1, f2, wq, wk, w2, bq, bk, zv, Q, K, VT);

    dim3 gs(S2_ / 128, S1_ / 128, B_);
    gemm_S<<<gs, 256, GEMM_SMEM>>>(Q, K, P, lp);

    lreduce_kernel<<<(B_ * S1_ + 255) / 256, 256>>>(lp, lv);

    dim3 gp(F_ / 128, S1_ / 128, B_);
    gemm_pv<<<gp, 256, GEMM_SMEM>>>(P, VT, lv, c2, out);
}